// round 13
// baseline (speedup 1.0000x reference)
#include <cuda_runtime.h>
#include <math.h>

#define B_    256
#define N_    512
#define SIG_  256
#define HID_  256
#define OUT_  10
#define H_    256

extern "C" __device__ float __nv_expf(float);

// ---------------- scratch (static device globals; no allocation) ----------------
__device__ float  g_prmf[16 * 8];
__device__ double g_logc[16];
__device__ float  g_loc [B_ * N_ * 2];
__device__ float  g_feat[B_ * N_ * 3];
__device__ float  g_bufA[B_ * N_ * HID_];      // t1
__device__ float  g_bufB[B_ * N_ * HID_];      // s1
__device__ float  g_bufC[B_ * N_ * HID_];      // s2
__device__ float  g_e1  [B_ * SIG_ * HID_];
__device__ float  g_e2  [B_ * SIG_ * HID_];
__device__ float  g_sig [B_ * SIG_];

// ---------------- packed f32x2 helpers (sm_103a) ----------------
__device__ __forceinline__ unsigned long long pack2(float lo, float hi)
{
    unsigned long long r;
    asm("mov.b64 %0, {%1, %2};" : "=l"(r) : "f"(lo), "f"(hi));
    return r;
}
__device__ __forceinline__ void unpack2(unsigned long long v, float& lo, float& hi)
{
    asm("mov.b64 {%0, %1}, %2;" : "=f"(lo), "=f"(hi) : "l"(v));
}
__device__ __forceinline__ void fma2(unsigned long long& acc,
                                     unsigned long long a, unsigned long long b)
{
    asm("fma.rn.f32x2 %0, %1, %2, %0;" : "+l"(acc) : "l"(a), "l"(b));
}
__device__ __forceinline__ float rcpa(float x)
{
    float r; asm("rcp.approx.f32 %0, %1;" : "=f"(r) : "f"(x)); return r;
}
__device__ __forceinline__ unsigned smem_u32(const void* p)
{
    return (unsigned)__cvta_generic_to_shared(p);
}
__device__ __forceinline__ void cp16(unsigned dst, const void* src)
{
    asm volatile("cp.async.cg.shared.global [%0], [%1], 16;" :: "r"(dst), "l"(src));
}
__device__ __forceinline__ void cp_commit()
{
    asm volatile("cp.async.commit_group;");
}
__device__ __forceinline__ void cp_wait1()
{
    asm volatile("cp.async.wait_group 1;");
}

// ---------------------------------------------------------------------------
// FROZEN decision-chain functions (validated R10). DO NOT TOUCH.
// ---------------------------------------------------------------------------
__device__ __forceinline__ float tanh_rational_fma(float x)
{
    const float kClamp = 7.90531110763549805f;
    float xc = fminf(fmaxf(x, -kClamp), kClamp);
    float x2 = __fmul_rn(xc, xc);
    float p = -2.76076847742355e-16f;
    p = __fmaf_rn(x2, p,  2.00018790482477e-13f);
    p = __fmaf_rn(x2, p, -8.60467152213735e-11f);
    p = __fmaf_rn(x2, p,  5.12229709037114e-08f);
    p = __fmaf_rn(x2, p,  1.48572235717979e-05f);
    p = __fmaf_rn(x2, p,  6.37261928875436e-04f);
    p = __fmaf_rn(x2, p,  4.89352455891786e-03f);
    float num = __fmul_rn(xc, p);
    float q = 1.19825839466702e-06f;
    q = __fmaf_rn(x2, q,  1.18534705686654e-04f);
    q = __fmaf_rn(x2, q,  2.26843463243900e-03f);
    q = __fmaf_rn(x2, q,  4.89352518554385e-03f);
    float r = __fdiv_rn(num, q);
    return (fabsf(x) < 0.0004f) ? x : r;
}

__device__ __forceinline__ float exp_cephes_fma(float x)
{
    const float kLog2e = 1.44269504088896341f;
    const float kC1 = 0.693359375f;
    const float kC2 = -2.12194440e-4f;
    float m = floorf(__fmaf_rn(x, kLog2e, 0.5f));
    float r = __fmaf_rn(m, -kC1, x);
    r = __fmaf_rn(m, -kC2, r);
    float r2 = __fmul_rn(r, r);
    float p = 1.9875691500E-4f;
    p = __fmaf_rn(p, r, 1.3981999507E-3f);
    p = __fmaf_rn(p, r, 8.3334519073E-3f);
    p = __fmaf_rn(p, r, 4.1665795894E-2f);
    p = __fmaf_rn(p, r, 1.6666665459E-1f);
    p = __fmaf_rn(p, r, 5.0000001201E-1f);
    p = __fmaf_rn(p, r2, r);
    p = __fadd_rn(p, 1.0f);
    int mi = (int)m;
    float two_m = __uint_as_float((unsigned)(mi + 127) << 23);
    return __fmul_rn(p, two_m);
}

// ---------------------------------------------------------------------------
// Kernel 0: per-group params (FROZEN decision bits)
// ---------------------------------------------------------------------------
__global__ void prep_kernel(const float* __restrict__ mg,
                            float* __restrict__ prm, double* __restrict__ logc)
{
    const int g = threadIdx.x;
    if (g >= 16) return;
    const float mux = mg[g * 6 + 1];
    const float muy = mg[g * 6 + 2];
    const float sx  = exp_cephes_fma(mg[g * 6 + 3]);
    const float sy  = exp_cephes_fma(mg[g * 6 + 4]);
    const float rho = tanh_rational_fma(mg[g * 6 + 5]);
    const float omr2 = __fsub_rn(1.0f, __fmul_rn(rho, rho));
    const float somr = __fsqrt_rn(omr2);
    prm[g * 8 + 0] = mux;  prm[g * 8 + 1] = muy;
    prm[g * 8 + 2] = sx;   prm[g * 8 + 3] = sy;
    prm[g * 8 + 4] = rho;  prm[g * 8 + 5] = somr;
    logc[g] = -1.8378770664093453 - log((double)sx * (double)sy)
              - 0.5 * log((double)omr2);
}

// ---------------------------------------------------------------------------
// Kernel 1: sampler (FROZEN decision chain)
// ---------------------------------------------------------------------------
__global__ void sampler_kernel(const float* __restrict__ x,
                               const float* __restrict__ z,
                               const float* __restrict__ prm,
                               const double* __restrict__ logcv,
                               float* __restrict__ loc,
                               float* __restrict__ feat,
                               float* __restrict__ flp)
{
    const int b = blockIdx.x;
    const int n = threadIdx.x;

    __shared__ float  s_feat[N_ * 3];
    __shared__ double s_red[N_];

    const int g = n >> 5;
    const float mux  = prm[g * 8 + 0];
    const float muy  = prm[g * 8 + 1];
    const float sx   = prm[g * 8 + 2];
    const float sy   = prm[g * 8 + 3];
    const float rho  = prm[g * 8 + 4];
    const float somr = prm[g * 8 + 5];

    const float z1 = z[((long)b * N_ + n) * 2 + 0];
    const float z2 = z[((long)b * N_ + n) * 2 + 1];

    const float xs = __fadd_rn(mux, __fmul_rn(sx, z1));
    const float tt = __fadd_rn(__fmul_rn(rho, z1), __fmul_rn(somr, z2));
    const float ys = __fadd_rn(muy, __fmul_rn(sy, tt));

    const float l0 = tanh_rational_fma(xs);
    const float l1 = tanh_rational_fma(ys);
    loc[((long)b * N_ + n) * 2 + 0] = l0;
    loc[((long)b * N_ + n) * 2 + 1] = l1;

    float p0f = __fsub_rn(__fmul_rn(__fmul_rn(0.5f, __fadd_rn(l0, 1.0f)), 256.0f), 0.1f);
    float p1f = __fsub_rn(__fmul_rn(__fmul_rn(0.5f, __fadd_rn(l1, 1.0f)), 256.0f), 0.1f);
    int p0 = (int)truncf(p0f);
    int p1 = (int)truncf(p1f);
    p0 = min(max(p0, 0), H_ - 1);
    p1 = min(max(p1, 0), H_ - 1);
    const float pv = x[(long)b * H_ * H_ + (long)p0 * H_ + p1];

    s_feat[n * 3 + 0] = pv;
    s_feat[n * 3 + 1] = l0;
    s_feat[n * 3 + 2] = l1;

    {
        const double dx = (double)xs - (double)mux;
        const double dy = (double)ys - (double)muy;
        const double sxd = (double)sx, syd = (double)sy, rhod = (double)rho;
        const double omr2 = 1.0 - rhod * rhod;
        const double quad = (dx * dx / (sxd * sxd)
                             - 2.0 * rhod * dx * dy / (sxd * syd)
                             + dy * dy / (syd * syd)) / omr2;
        s_red[n] = logcv[g] - 0.5 * quad;
    }
    __syncthreads();
    for (int st = 256; st > 0; st >>= 1) {
        if (n < st) s_red[n] += s_red[n + st];
        __syncthreads();
    }
    if (n == 0) flp[b] = (float)s_red[0];

    float* fb = feat + (long)b * (N_ * 3);
    for (int i = n; i < N_ * 3; i += N_) fb[i] = s_feat[i];
}

// ---------------------------------------------------------------------------
// Kernel 1b: g = adj @ feat (3 cols), s1 = relu(g @ W1 + b1)
// ---------------------------------------------------------------------------
__global__ void __launch_bounds__(512)
adj_feat_s1_kernel(const float* __restrict__ loc,
                   const float* __restrict__ feat,
                   const float* __restrict__ gc1w,
                   const float* __restrict__ gc1b,
                   float* __restrict__ s1)
{
    const int b = blockIdx.x;
    const int n = threadIdx.x;

    __shared__ float lx[N_], ly[N_];
    __shared__ float fm[N_ * 3];
    __shared__ float w[3 * HID_];
    __shared__ float bias[HID_];
    __shared__ float gsm[N_ * 3];

    const float* locb = loc + (long)b * N_ * 2;
    const float* fb   = feat + (long)b * N_ * 3;

    lx[n] = locb[2 * n + 0];
    ly[n] = locb[2 * n + 1];
    for (int i = n; i < N_ * 3; i += N_) fm[i] = fb[i];
    for (int i = n; i < 3 * HID_; i += N_) w[i] = gc1w[i];
    if (n < HID_) bias[n] = gc1b[n];
    __syncthreads();

    const float myx = lx[n], myy = ly[n];
    float g0 = 0.0f, g1 = 0.0f, g2 = 0.0f;
#pragma unroll 4
    for (int m = 0; m < N_; m++) {
        const float dxx = __fsub_rn(myx, lx[m]);
        const float dyy = __fsub_rn(myy, ly[m]);
        const float d2  = __fadd_rn(__fmul_rn(dxx, dxx), __fmul_rn(dyy, dyy));
        const float a   = rcpa(__fmaf_rn(0.5f, d2, 1.0f));
        g0 = __fmaf_rn(a, fm[m * 3 + 0], g0);
        g1 = __fmaf_rn(a, fm[m * 3 + 1], g1);
        g2 = __fmaf_rn(a, fm[m * 3 + 2], g2);
    }
    gsm[n * 3 + 0] = g0;
    gsm[n * 3 + 1] = g1;
    gsm[n * 3 + 2] = g2;
    __syncthreads();

    float* s1b = s1 + (long)b * (N_ * HID_);
    for (int r = 0; r < 256; r++) {
        const int idx = r * N_ + n;
        const int nn = idx >> 8;
        const int hh = idx & (HID_ - 1);
        float v = __fmaf_rn(gsm[nn * 3 + 2], w[2 * HID_ + hh],
                  __fmaf_rn(gsm[nn * 3 + 1], w[HID_ + hh],
                  __fmaf_rn(gsm[nn * 3 + 0], w[hh], bias[hh])));
        s1b[idx] = fmaxf(v, 0.0f);
    }
}

// ---------------------------------------------------------------------------
// Kernel 2: batched SGEMM, 128x128x8, f32x2, A reg-prefetch (2-stage),
// B via cp.async (3-stage — covers DRAM latency across 2 chunks).
// ---------------------------------------------------------------------------
__global__ void __launch_bounds__(256, 2)
sgemm128(const float* __restrict__ A, int lda, long strideA,
         const float* __restrict__ Bm, int ldb, long strideB,
         float* __restrict__ C, int ldc, long strideC)
{
    __shared__ float As[2][8][128];
    __shared__ float Bs[3][8][128];

    const int bz = blockIdx.z;
    A  += (long)bz * strideA;
    Bm += (long)bz * strideB;
    C  += (long)bz * strideC;

    const int m0 = blockIdx.y * 128;
    const int n0 = blockIdx.x * 128;
    const int tid = threadIdx.x;
    const int ty = tid >> 4;
    const int tx = tid & 15;

    const int aRow = tid >> 1;
    const int aCol = (tid & 1) * 4;
    const int bRow = tid >> 5;
    const int bCol = (tid & 31) * 4;

    const int K = lda;
    const int nk = K >> 3;

    unsigned long long acc2[4][8];
#pragma unroll
    for (int i = 0; i < 4; i++)
#pragma unroll
        for (int j = 0; j < 8; j++) acc2[i][j] = 0ull;

    // prologue: B0, B1 via cp.async; A0 via regs
    cp16(smem_u32(&Bs[0][bRow][bCol]), Bm + (long)bRow * ldb + n0 + bCol);
    cp_commit();
    cp16(smem_u32(&Bs[1][bRow][bCol]), Bm + (long)(8 + bRow) * ldb + n0 + bCol);
    cp_commit();
    {
        float4 av = *(const float4*)(A + (long)(m0 + aRow) * lda + aCol);
        As[0][aCol + 0][aRow] = av.x;
        As[0][aCol + 1][aRow] = av.y;
        As[0][aCol + 2][aRow] = av.z;
        As[0][aCol + 3][aRow] = av.w;
    }
    cp_wait1();           // B0 arrived
    __syncthreads();

    for (int t = 0; t < nk; t++) {
        const int bufA = t & 1;
        const int bufB = t % 3;
        const bool moreA = (t + 1 < nk);
        const bool moreB = (t + 2 < nk);

        float4 av;
        if (moreA) {
            const int k0 = (t + 1) << 3;
            av = *(const float4*)(A + (long)(m0 + aRow) * lda + k0 + aCol);
        }
        if (moreB) {
            const int k0 = (t + 2) << 3;
            cp16(smem_u32(&Bs[(t + 2) % 3][bRow][bCol]),
                 Bm + (long)(k0 + bRow) * ldb + n0 + bCol);
        }
        cp_commit();      // always commit (keeps group accounting uniform)

#pragma unroll
        for (int k = 0; k < 8; k++) {
            unsigned long long a2[4];
#pragma unroll
            for (int i = 0; i < 4; i++)
                a2[i] = *(const unsigned long long*)&As[bufA][k][ty * 8 + 2 * i];
            float4 b0 = *(const float4*)&Bs[bufB][k][tx * 8];
            float4 b1 = *(const float4*)&Bs[bufB][k][tx * 8 + 4];
            unsigned long long bd[8];
            bd[0] = pack2(b0.x, b0.x); bd[1] = pack2(b0.y, b0.y);
            bd[2] = pack2(b0.z, b0.z); bd[3] = pack2(b0.w, b0.w);
            bd[4] = pack2(b1.x, b1.x); bd[5] = pack2(b1.y, b1.y);
            bd[6] = pack2(b1.z, b1.z); bd[7] = pack2(b1.w, b1.w);
#pragma unroll
            for (int i = 0; i < 4; i++)
#pragma unroll
                for (int j = 0; j < 8; j++)
                    fma2(acc2[i][j], a2[i], bd[j]);
        }

        if (moreA) {
            const int nb = bufA ^ 1;
            As[nb][aCol + 0][aRow] = av.x;
            As[nb][aCol + 1][aRow] = av.y;
            As[nb][aCol + 2][aRow] = av.z;
            As[nb][aCol + 3][aRow] = av.w;
        }
        cp_wait1();       // B(t+1) arrived (1 group may stay in flight)
        __syncthreads();
    }

#pragma unroll
    for (int i = 0; i < 4; i++) {
        float lo[8], hi[8];
#pragma unroll
        for (int j = 0; j < 8; j++) unpack2(acc2[i][j], lo[j], hi[j]);
        float* cp0 = C + (long)(m0 + ty * 8 + 2 * i) * ldc + n0 + tx * 8;
        float* cp1 = cp0 + ldc;
        *(float4*)(cp0)     = make_float4(lo[0], lo[1], lo[2], lo[3]);
        *(float4*)(cp0 + 4) = make_float4(lo[4], lo[5], lo[6], lo[7]);
        *(float4*)(cp1)     = make_float4(hi[0], hi[1], hi[2], hi[3]);
        *(float4*)(cp1 + 4) = make_float4(hi[4], hi[5], hi[6], hi[7]);
    }
}

// ---------------------------------------------------------------------------
// Kernel 3: adj-GEMM (s2), adj generated on the fly, B via cp.async 3-stage.
// ---------------------------------------------------------------------------
__global__ void __launch_bounds__(256, 2)
sgemm_adj(const float* __restrict__ loc,
          const float* __restrict__ Hin,
          const float* __restrict__ bias,
          float* __restrict__ Out)
{
    __shared__ float As[2][8][128];
    __shared__ float Bs[3][8][128];
    __shared__ float lnx[128], lny[128];

    const int b = blockIdx.z;
    const float* locb = loc + (long)b * N_ * 2;
    const float* Bb   = Hin + (long)b * N_ * HID_;
    float*       Cb   = Out + (long)b * N_ * HID_;

    const int m0 = blockIdx.y * 128;
    const int n0 = blockIdx.x * 128;
    const int tid = threadIdx.x;
    const int ty = tid >> 4, tx = tid & 15;
    const int bRow = tid >> 5, bCol = (tid & 31) * 4;

    const int kbase = tid >> 7;
    const int mcol  = tid & 127;

    if (tid < 128) {
        lnx[tid] = locb[(m0 + tid) * 2 + 0];
        lny[tid] = locb[(m0 + tid) * 2 + 1];
    }
    __syncthreads();

    const int nk = N_ >> 3;

    unsigned long long acc2[4][8];
#pragma unroll
    for (int i = 0; i < 4; i++)
#pragma unroll
        for (int j = 0; j < 8; j++) acc2[i][j] = 0ull;

    // prologue
    cp16(smem_u32(&Bs[0][bRow][bCol]), Bb + (long)bRow * HID_ + n0 + bCol);
    cp_commit();
    cp16(smem_u32(&Bs[1][bRow][bCol]), Bb + (long)(8 + bRow) * HID_ + n0 + bCol);
    cp_commit();
    {
        const float lx = lnx[mcol], ly = lny[mcol];
#pragma unroll
        for (int i = 0; i < 4; i++) {
            const int k = kbase + 2 * i;
            const float dxx = __fsub_rn(lx, locb[2 * k + 0]);
            const float dyy = __fsub_rn(ly, locb[2 * k + 1]);
            const float d2 = __fadd_rn(__fmul_rn(dxx, dxx), __fmul_rn(dyy, dyy));
            As[0][k][mcol] = rcpa(__fadd_rn(1.0f, __fmul_rn(0.5f, d2)));
        }
    }
    cp_wait1();
    __syncthreads();

    for (int t = 0; t < nk; t++) {
        const int bufA = t & 1;
        const int bufB = t % 3;
        const bool moreA = (t + 1 < nk);
        const bool moreB = (t + 2 < nk);

        float nextAdj[4];
        if (moreA) {
            const int k0 = (t + 1) << 3;
            const float lx = lnx[mcol], ly = lny[mcol];
#pragma unroll
            for (int i = 0; i < 4; i++) {
                const int k = k0 + kbase + 2 * i;
                const float dxx = __fsub_rn(lx, locb[2 * k + 0]);
                const float dyy = __fsub_rn(ly, locb[2 * k + 1]);
                const float d2 = __fadd_rn(__fmul_rn(dxx, dxx), __fmul_rn(dyy, dyy));
                nextAdj[i] = rcpa(__fadd_rn(1.0f, __fmul_rn(0.5f, d2)));
            }
        }
        if (moreB) {
            const int k0 = (t + 2) << 3;
            cp16(smem_u32(&Bs[(t + 2) % 3][bRow][bCol]),
                 Bb + (long)(k0 + bRow) * HID_ + n0 + bCol);
        }
        cp_commit();

#pragma unroll
        for (int k = 0; k < 8; k++) {
            unsigned long long a2[4];
#pragma unroll
            for (int i = 0; i < 4; i++)
                a2[i] = *(const unsigned long long*)&As[bufA][k][ty * 8 + 2 * i];
            float4 b0 = *(const float4*)&Bs[bufB][k][tx * 8];
            float4 b1 = *(const float4*)&Bs[bufB][k][tx * 8 + 4];
            unsigned long long bd[8];
            bd[0] = pack2(b0.x, b0.x); bd[1] = pack2(b0.y, b0.y);
            bd[2] = pack2(b0.z, b0.z); bd[3] = pack2(b0.w, b0.w);
            bd[4] = pack2(b1.x, b1.x); bd[5] = pack2(b1.y, b1.y);
            bd[6] = pack2(b1.z, b1.z); bd[7] = pack2(b1.w, b1.w);
#pragma unroll
            for (int i = 0; i < 4; i++)
#pragma unroll
                for (int j = 0; j < 8; j++)
                    fma2(acc2[i][j], a2[i], bd[j]);
        }

        if (moreA) {
            const int nb = bufA ^ 1;
#pragma unroll
            for (int i = 0; i < 4; i++)
                As[nb][kbase + 2 * i][mcol] = nextAdj[i];
        }
        cp_wait1();
        __syncthreads();
    }

#pragma unroll
    for (int i = 0; i < 4; i++) {
        float lo[8], hi[8];
#pragma unroll
        for (int j = 0; j < 8; j++) {
            unpack2(acc2[i][j], lo[j], hi[j]);
            const float bb = bias[n0 + tx * 8 + j];
            lo[j] = fmaxf(__fadd_rn(lo[j], bb), 0.0f);
            hi[j] = fmaxf(__fadd_rn(hi[j], bb), 0.0f);
        }
        float* cp0 = Cb + (long)(m0 + ty * 8 + 2 * i) * HID_ + n0 + tx * 8;
        float* cp1 = cp0 + HID_;
        *(float4*)(cp0)     = make_float4(lo[0], lo[1], lo[2], lo[3]);
        *(float4*)(cp0 + 4) = make_float4(lo[4], lo[5], lo[6], lo[7]);
        *(float4*)(cp1)     = make_float4(hi[0], hi[1], hi[2], hi[3]);
        *(float4*)(cp1 + 4) = make_float4(hi[4], hi[5], hi[6], hi[7]);
    }
}

// ---------------------------------------------------------------------------
// Kernel 4: softmax over batch axis for e1, e2; sig[b,s] = sum_h(g1+g2)
// ---------------------------------------------------------------------------
__global__ void softmax_sig_kernel(const float* __restrict__ e1,
                                   const float* __restrict__ e2,
                                   float* __restrict__ sig)
{
    const int s = blockIdx.x;
    const int h = threadIdx.x;
    const long base = (long)s * HID_ + h;
    const long bs = (long)SIG_ * HID_;

    float m1 = -1e30f, m2 = -1e30f;
    for (int b = 0; b < B_; b++) {
        m1 = fmaxf(m1, e1[base + (long)b * bs]);
        m2 = fmaxf(m2, e2[base + (long)b * bs]);
    }
    float d1 = 0.0f, d2 = 0.0f;
    for (int b = 0; b < B_; b++) {
        d1 += __nv_expf(e1[base + (long)b * bs] - m1);
        d2 += __nv_expf(e2[base + (long)b * bs] - m2);
    }
    const float i1 = 1.0f / d1, i2 = 1.0f / d2;

    __shared__ float red[8];
    const int lane = h & 31, warp = h >> 5;
    for (int b = 0; b < B_; b++) {
        float c = __nv_expf(e1[base + (long)b * bs] - m1) * i1
                + __nv_expf(e2[base + (long)b * bs] - m2) * i2;
#pragma unroll
        for (int o = 16; o > 0; o >>= 1) c += __shfl_down_sync(0xffffffffu, c, o);
        if (lane == 0) red[warp] = c;
        __syncthreads();
        if (h == 0) {
            float t = 0.0f;
#pragma unroll
            for (int w = 0; w < 8; w++) t += red[w];
            sig[(long)b * SIG_ + s] = t;
        }
        __syncthreads();
    }
}

// ---------------------------------------------------------------------------
// Kernel 5: out[b,:] = softmax(sig[b,:] @ fcf_w^T + fcf_b). One warp per batch.
// ---------------------------------------------------------------------------
__global__ void final_kernel(const float* __restrict__ sig,
                             const float* __restrict__ fw,
                             const float* __restrict__ fb,
                             float* __restrict__ out)
{
    const int b = blockIdx.x;
    const int lane = threadIdx.x;
    float logits[OUT_];
#pragma unroll
    for (int o = 0; o < OUT_; o++) {
        float p = 0.0f;
        for (int s = lane; s < SIG_; s += 32)
            p = __fmaf_rn(sig[(long)b * SIG_ + s], fw[(long)o * SIG_ + s], p);
#pragma unroll
        for (int off = 16; off > 0; off >>= 1)
            p += __shfl_down_sync(0xffffffffu, p, off);
        p = __shfl_sync(0xffffffffu, p, 0);
        logits[o] = p + fb[o];
    }
    if (lane == 0) {
        float mx = -1e30f;
#pragma unroll
        for (int o = 0; o < OUT_; o++) mx = fmaxf(mx, logits[o]);
        float e[OUT_], ssum = 0.0f;
#pragma unroll
        for (int o = 0; o < OUT_; o++) { e[o] = __nv_expf(logits[o] - mx); ssum += e[o]; }
        const float inv = 1.0f / ssum;
#pragma unroll
        for (int o = 0; o < OUT_; o++) out[(long)b * OUT_ + o] = e[o] * inv;
    }
}

// ---------------------------------------------------------------------------
extern "C" void kernel_launch(void* const* d_in, const int* in_sizes, int n_in,
                              void* d_out, int out_size)
{
    const float* x     = (const float*)d_in[0];
    const float* z     = (const float*)d_in[2];
    const float* mg    = (const float*)d_in[3];
    const float* gc1w  = (const float*)d_in[4];
    const float* gc1b  = (const float*)d_in[5];
    const float* gc2w  = (const float*)d_in[6];
    const float* gc2b  = (const float*)d_in[7];
    const float* coll1 = (const float*)d_in[8];
    const float* coll2 = (const float*)d_in[9];
    const float* fcfw  = (const float*)d_in[10];
    const float* fcfb  = (const float*)d_in[11];
    float* outp = (float*)d_out;

    float *prmf, *loc, *feat, *bufA, *bufB, *bufC, *e1, *e2, *sig;
    double* logc;
    cudaGetSymbolAddress((void**)&prmf, g_prmf);
    cudaGetSymbolAddress((void**)&logc, g_logc);
    cudaGetSymbolAddress((void**)&loc,  g_loc);
    cudaGetSymbolAddress((void**)&feat, g_feat);
    cudaGetSymbolAddress((void**)&bufA, g_bufA);
    cudaGetSymbolAddress((void**)&bufB, g_bufB);
    cudaGetSymbolAddress((void**)&bufC, g_bufC);
    cudaGetSymbolAddress((void**)&e1,   g_e1);
    cudaGetSymbolAddress((void**)&e2,   g_e2);
    cudaGetSymbolAddress((void**)&sig,  g_sig);

    // one-time side stream + events (host objects only; no device allocation)
    static cudaStream_t s1s = nullptr;
    static cudaEvent_t evA = nullptr, ev1 = nullptr;
    if (s1s == nullptr) {
        cudaStreamCreateWithFlags(&s1s, cudaStreamNonBlocking);
        cudaEventCreateWithFlags(&evA, cudaEventDisableTiming);
        cudaEventCreateWithFlags(&ev1, cudaEventDisableTiming);
    }

    const long BS = (long)N_ * HID_;
    const long ES = (long)SIG_ * HID_;

    prep_kernel<<<1, 32>>>(mg, prmf, logc);
    sampler_kernel<<<B_, N_>>>(x, z, prmf, logc, loc, feat, outp + B_ * OUT_);
    adj_feat_s1_kernel<<<B_, N_>>>(loc, feat, gc1w, gc1b, bufB);   // s1

    // fork: e1 = coll1 @ s1 on side stream (overlaps t1 -> s2 chain)
    cudaEventRecord(evA, 0);
    cudaStreamWaitEvent(s1s, evA, 0);
    sgemm128<<<dim3(2, 2, B_), 256, 0, s1s>>>(coll1, 512, 0, bufB, 256, BS, e1, 256, ES);
    cudaEventRecord(ev1, s1s);

    // main chain
    sgemm128<<<dim3(2, 4, B_), 256>>>(bufB, 256, BS, gc2w, 256, 0, bufA, 256, BS);  // t1
    sgemm_adj<<<dim3(2, 4, B_), 256>>>(loc, bufA, gc2b, bufC);                      // s2
    sgemm128<<<dim3(2, 2, B_), 256>>>(coll2, 512, 0, bufC, 256, BS, e2, 256, ES);   // e2

    // join
    cudaStreamWaitEvent(0, ev1, 0);
    softmax_sig_kernel<<<SIG_, HID_>>>(e1, e2, sig);
    final_kernel<<<B_, 32>>>(sig, fcfw, fcfb, outp);
}

// round 14
// speedup vs baseline: 1.0830x; 1.0830x over previous
#include <cuda_runtime.h>
#include <math.h>

#define B_    256
#define N_    512
#define SIG_  256
#define HID_  256
#define OUT_  10
#define H_    256

extern "C" __device__ float __nv_expf(float);

// ---------------- scratch (static device globals; no allocation) ----------------
__device__ float  g_prmf[16 * 8];
__device__ double g_logc[16];
__device__ float  g_loc [B_ * N_ * 2];
__device__ float  g_feat[B_ * N_ * 3];
__device__ float  g_bufA[B_ * N_ * HID_];      // t1
__device__ float  g_bufB[B_ * N_ * HID_];      // s1
__device__ float  g_bufC[B_ * N_ * HID_];      // s2
__device__ float  g_e1  [B_ * SIG_ * HID_];
__device__ float  g_e2  [B_ * SIG_ * HID_];
__device__ float  g_sig [B_ * SIG_];

// ---------------- packed f32x2 helpers (sm_103a) ----------------
__device__ __forceinline__ unsigned long long pack2(float lo, float hi)
{
    unsigned long long r;
    asm("mov.b64 %0, {%1, %2};" : "=l"(r) : "f"(lo), "f"(hi));
    return r;
}
__device__ __forceinline__ void unpack2(unsigned long long v, float& lo, float& hi)
{
    asm("mov.b64 {%0, %1}, %2;" : "=f"(lo), "=f"(hi) : "l"(v));
}
__device__ __forceinline__ void fma2(unsigned long long& acc,
                                     unsigned long long a, unsigned long long b)
{
    asm("fma.rn.f32x2 %0, %1, %2, %0;" : "+l"(acc) : "l"(a), "l"(b));
}
__device__ __forceinline__ float rcpa(float x)
{
    float r; asm("rcp.approx.f32 %0, %1;" : "=f"(r) : "f"(x)); return r;
}

// ---------------------------------------------------------------------------
// FROZEN decision-chain functions (validated R10). DO NOT TOUCH.
// ---------------------------------------------------------------------------
__device__ __forceinline__ float tanh_rational_fma(float x)
{
    const float kClamp = 7.90531110763549805f;
    float xc = fminf(fmaxf(x, -kClamp), kClamp);
    float x2 = __fmul_rn(xc, xc);
    float p = -2.76076847742355e-16f;
    p = __fmaf_rn(x2, p,  2.00018790482477e-13f);
    p = __fmaf_rn(x2, p, -8.60467152213735e-11f);
    p = __fmaf_rn(x2, p,  5.12229709037114e-08f);
    p = __fmaf_rn(x2, p,  1.48572235717979e-05f);
    p = __fmaf_rn(x2, p,  6.37261928875436e-04f);
    p = __fmaf_rn(x2, p,  4.89352455891786e-03f);
    float num = __fmul_rn(xc, p);
    float q = 1.19825839466702e-06f;
    q = __fmaf_rn(x2, q,  1.18534705686654e-04f);
    q = __fmaf_rn(x2, q,  2.26843463243900e-03f);
    q = __fmaf_rn(x2, q,  4.89352518554385e-03f);
    float r = __fdiv_rn(num, q);
    return (fabsf(x) < 0.0004f) ? x : r;
}

__device__ __forceinline__ float exp_cephes_fma(float x)
{
    const float kLog2e = 1.44269504088896341f;
    const float kC1 = 0.693359375f;
    const float kC2 = -2.12194440e-4f;
    float m = floorf(__fmaf_rn(x, kLog2e, 0.5f));
    float r = __fmaf_rn(m, -kC1, x);
    r = __fmaf_rn(m, -kC2, r);
    float r2 = __fmul_rn(r, r);
    float p = 1.9875691500E-4f;
    p = __fmaf_rn(p, r, 1.3981999507E-3f);
    p = __fmaf_rn(p, r, 8.3334519073E-3f);
    p = __fmaf_rn(p, r, 4.1665795894E-2f);
    p = __fmaf_rn(p, r, 1.6666665459E-1f);
    p = __fmaf_rn(p, r, 5.0000001201E-1f);
    p = __fmaf_rn(p, r2, r);
    p = __fadd_rn(p, 1.0f);
    int mi = (int)m;
    float two_m = __uint_as_float((unsigned)(mi + 127) << 23);
    return __fmul_rn(p, two_m);
}

// ---------------------------------------------------------------------------
// Kernel 0: per-group params (FROZEN decision bits)
// ---------------------------------------------------------------------------
__global__ void prep_kernel(const float* __restrict__ mg,
                            float* __restrict__ prm, double* __restrict__ logc)
{
    const int g = threadIdx.x;
    if (g >= 16) return;
    const float mux = mg[g * 6 + 1];
    const float muy = mg[g * 6 + 2];
    const float sx  = exp_cephes_fma(mg[g * 6 + 3]);
    const float sy  = exp_cephes_fma(mg[g * 6 + 4]);
    const float rho = tanh_rational_fma(mg[g * 6 + 5]);
    const float omr2 = __fsub_rn(1.0f, __fmul_rn(rho, rho));
    const float somr = __fsqrt_rn(omr2);
    prm[g * 8 + 0] = mux;  prm[g * 8 + 1] = muy;
    prm[g * 8 + 2] = sx;   prm[g * 8 + 3] = sy;
    prm[g * 8 + 4] = rho;  prm[g * 8 + 5] = somr;
    logc[g] = -1.8378770664093453 - log((double)sx * (double)sy)
              - 0.5 * log((double)omr2);
}

// ---------------------------------------------------------------------------
// Kernel 1: sampler (FROZEN decision chain)
// ---------------------------------------------------------------------------
__global__ void sampler_kernel(const float* __restrict__ x,
                               const float* __restrict__ z,
                               const float* __restrict__ prm,
                               const double* __restrict__ logcv,
                               float* __restrict__ loc,
                               float* __restrict__ feat,
                               float* __restrict__ flp)
{
    const int b = blockIdx.x;
    const int n = threadIdx.x;

    __shared__ float  s_feat[N_ * 3];
    __shared__ double s_red[N_];

    const int g = n >> 5;
    const float mux  = prm[g * 8 + 0];
    const float muy  = prm[g * 8 + 1];
    const float sx   = prm[g * 8 + 2];
    const float sy   = prm[g * 8 + 3];
    const float rho  = prm[g * 8 + 4];
    const float somr = prm[g * 8 + 5];

    const float z1 = z[((long)b * N_ + n) * 2 + 0];
    const float z2 = z[((long)b * N_ + n) * 2 + 1];

    const float xs = __fadd_rn(mux, __fmul_rn(sx, z1));
    const float tt = __fadd_rn(__fmul_rn(rho, z1), __fmul_rn(somr, z2));
    const float ys = __fadd_rn(muy, __fmul_rn(sy, tt));

    const float l0 = tanh_rational_fma(xs);
    const float l1 = tanh_rational_fma(ys);
    loc[((long)b * N_ + n) * 2 + 0] = l0;
    loc[((long)b * N_ + n) * 2 + 1] = l1;

    float p0f = __fsub_rn(__fmul_rn(__fmul_rn(0.5f, __fadd_rn(l0, 1.0f)), 256.0f), 0.1f);
    float p1f = __fsub_rn(__fmul_rn(__fmul_rn(0.5f, __fadd_rn(l1, 1.0f)), 256.0f), 0.1f);
    int p0 = (int)truncf(p0f);
    int p1 = (int)truncf(p1f);
    p0 = min(max(p0, 0), H_ - 1);
    p1 = min(max(p1, 0), H_ - 1);
    const float pv = x[(long)b * H_ * H_ + (long)p0 * H_ + p1];

    s_feat[n * 3 + 0] = pv;
    s_feat[n * 3 + 1] = l0;
    s_feat[n * 3 + 2] = l1;

    {
        const double dx = (double)xs - (double)mux;
        const double dy = (double)ys - (double)muy;
        const double sxd = (double)sx, syd = (double)sy, rhod = (double)rho;
        const double omr2 = 1.0 - rhod * rhod;
        const double quad = (dx * dx / (sxd * sxd)
                             - 2.0 * rhod * dx * dy / (sxd * syd)
                             + dy * dy / (syd * syd)) / omr2;
        s_red[n] = logcv[g] - 0.5 * quad;
    }
    __syncthreads();
    for (int st = 256; st > 0; st >>= 1) {
        if (n < st) s_red[n] += s_red[n + st];
        __syncthreads();
    }
    if (n == 0) flp[b] = (float)s_red[0];

    float* fb = feat + (long)b * (N_ * 3);
    for (int i = n; i < N_ * 3; i += N_) fb[i] = s_feat[i];
}

// ---------------------------------------------------------------------------
// Kernel 1b: g = adj @ feat (3 cols), s1 = relu(g @ W1 + b1)
// ---------------------------------------------------------------------------
__global__ void __launch_bounds__(512)
adj_feat_s1_kernel(const float* __restrict__ loc,
                   const float* __restrict__ feat,
                   const float* __restrict__ gc1w,
                   const float* __restrict__ gc1b,
                   float* __restrict__ s1)
{
    const int b = blockIdx.x;
    const int n = threadIdx.x;

    __shared__ float lx[N_], ly[N_];
    __shared__ float fm[N_ * 3];
    __shared__ float w[3 * HID_];
    __shared__ float bias[HID_];
    __shared__ float gsm[N_ * 3];

    const float* locb = loc + (long)b * N_ * 2;
    const float* fb   = feat + (long)b * N_ * 3;

    lx[n] = locb[2 * n + 0];
    ly[n] = locb[2 * n + 1];
    for (int i = n; i < N_ * 3; i += N_) fm[i] = fb[i];
    for (int i = n; i < 3 * HID_; i += N_) w[i] = gc1w[i];
    if (n < HID_) bias[n] = gc1b[n];
    __syncthreads();

    const float myx = lx[n], myy = ly[n];
    float g0 = 0.0f, g1 = 0.0f, g2 = 0.0f;
#pragma unroll 4
    for (int m = 0; m < N_; m++) {
        const float dxx = __fsub_rn(myx, lx[m]);
        const float dyy = __fsub_rn(myy, ly[m]);
        const float d2  = __fadd_rn(__fmul_rn(dxx, dxx), __fmul_rn(dyy, dyy));
        const float a   = rcpa(__fmaf_rn(0.5f, d2, 1.0f));
        g0 = __fmaf_rn(a, fm[m * 3 + 0], g0);
        g1 = __fmaf_rn(a, fm[m * 3 + 1], g1);
        g2 = __fmaf_rn(a, fm[m * 3 + 2], g2);
    }
    gsm[n * 3 + 0] = g0;
    gsm[n * 3 + 1] = g1;
    gsm[n * 3 + 2] = g2;
    __syncthreads();

    float* s1b = s1 + (long)b * (N_ * HID_);
    for (int r = 0; r < 256; r++) {
        const int idx = r * N_ + n;
        const int nn = idx >> 8;
        const int hh = idx & (HID_ - 1);
        float v = __fmaf_rn(gsm[nn * 3 + 2], w[2 * HID_ + hh],
                  __fmaf_rn(gsm[nn * 3 + 1], w[HID_ + hh],
                  __fmaf_rn(gsm[nn * 3 + 0], w[hh], bias[hh])));
        s1b[idx] = fmaxf(v, 0.0f);
    }
}

// ---------------------------------------------------------------------------
// Kernel 2: batched SGEMM, 128x128 tile, BK=16, register double-buffer,
// packed fma.rn.f32x2. Accumulation order identical to BK=8 version.
// ---------------------------------------------------------------------------
__global__ void __launch_bounds__(256, 2)
sgemm128(const float* __restrict__ A, int lda, long strideA,
         const float* __restrict__ Bm, int ldb, long strideB,
         float* __restrict__ C, int ldc, long strideC)
{
    __shared__ float As[2][16][128];
    __shared__ float Bs[2][16][128];

    const int bz = blockIdx.z;
    A  += (long)bz * strideA;
    Bm += (long)bz * strideB;
    C  += (long)bz * strideC;

    const int m0 = blockIdx.y * 128;
    const int n0 = blockIdx.x * 128;
    const int tid = threadIdx.x;
    const int ty = tid >> 4;
    const int tx = tid & 15;

    const int aRow = tid >> 1;             // 0..127
    const int aCol = (tid & 1) * 8;        // 0 or 8
    const int bRow = tid >> 4;             // 0..15
    const int bCol = (tid & 15) * 8;       // 0..120

    const int K = lda;
    const int nk = K >> 4;

    unsigned long long acc2[4][8];
#pragma unroll
    for (int i = 0; i < 4; i++)
#pragma unroll
        for (int j = 0; j < 8; j++) acc2[i][j] = 0ull;

    // prologue: chunk 0 -> buf 0
    {
        const float* ap = A + (long)(m0 + aRow) * lda + aCol;
        float4 a0 = *(const float4*)(ap);
        float4 a1 = *(const float4*)(ap + 4);
        As[0][aCol + 0][aRow] = a0.x; As[0][aCol + 1][aRow] = a0.y;
        As[0][aCol + 2][aRow] = a0.z; As[0][aCol + 3][aRow] = a0.w;
        As[0][aCol + 4][aRow] = a1.x; As[0][aCol + 5][aRow] = a1.y;
        As[0][aCol + 6][aRow] = a1.z; As[0][aCol + 7][aRow] = a1.w;
        const float* bp = Bm + (long)bRow * ldb + n0 + bCol;
        *(float4*)&Bs[0][bRow][bCol]     = *(const float4*)(bp);
        *(float4*)&Bs[0][bRow][bCol + 4] = *(const float4*)(bp + 4);
    }
    __syncthreads();

    for (int t = 0; t < nk; t++) {
        const int buf = t & 1;
        const bool more = (t + 1 < nk);
        float4 a0, a1, b0v, b1v;
        if (more) {
            const int k0 = (t + 1) << 4;
            const float* ap = A + (long)(m0 + aRow) * lda + k0 + aCol;
            a0 = *(const float4*)(ap);
            a1 = *(const float4*)(ap + 4);
            const float* bp = Bm + (long)(k0 + bRow) * ldb + n0 + bCol;
            b0v = *(const float4*)(bp);
            b1v = *(const float4*)(bp + 4);
        }

#pragma unroll
        for (int k = 0; k < 16; k++) {
            unsigned long long a2[4];
#pragma unroll
            for (int i = 0; i < 4; i++)
                a2[i] = *(const unsigned long long*)&As[buf][k][ty * 8 + 2 * i];
            float4 c0 = *(const float4*)&Bs[buf][k][tx * 8];
            float4 c1 = *(const float4*)&Bs[buf][k][tx * 8 + 4];
            unsigned long long bd[8];
            bd[0] = pack2(c0.x, c0.x); bd[1] = pack2(c0.y, c0.y);
            bd[2] = pack2(c0.z, c0.z); bd[3] = pack2(c0.w, c0.w);
            bd[4] = pack2(c1.x, c1.x); bd[5] = pack2(c1.y, c1.y);
            bd[6] = pack2(c1.z, c1.z); bd[7] = pack2(c1.w, c1.w);
#pragma unroll
            for (int i = 0; i < 4; i++)
#pragma unroll
                for (int j = 0; j < 8; j++)
                    fma2(acc2[i][j], a2[i], bd[j]);
        }

        if (more) {
            const int nb = buf ^ 1;
            As[nb][aCol + 0][aRow] = a0.x; As[nb][aCol + 1][aRow] = a0.y;
            As[nb][aCol + 2][aRow] = a0.z; As[nb][aCol + 3][aRow] = a0.w;
            As[nb][aCol + 4][aRow] = a1.x; As[nb][aCol + 5][aRow] = a1.y;
            As[nb][aCol + 6][aRow] = a1.z; As[nb][aCol + 7][aRow] = a1.w;
            *(float4*)&Bs[nb][bRow][bCol]     = b0v;
            *(float4*)&Bs[nb][bRow][bCol + 4] = b1v;
        }
        __syncthreads();
    }

#pragma unroll
    for (int i = 0; i < 4; i++) {
        float lo[8], hi[8];
#pragma unroll
        for (int j = 0; j < 8; j++) unpack2(acc2[i][j], lo[j], hi[j]);
        float* cp0 = C + (long)(m0 + ty * 8 + 2 * i) * ldc + n0 + tx * 8;
        float* cp1 = cp0 + ldc;
        *(float4*)(cp0)     = make_float4(lo[0], lo[1], lo[2], lo[3]);
        *(float4*)(cp0 + 4) = make_float4(lo[4], lo[5], lo[6], lo[7]);
        *(float4*)(cp1)     = make_float4(hi[0], hi[1], hi[2], hi[3]);
        *(float4*)(cp1 + 4) = make_float4(hi[4], hi[5], hi[6], hi[7]);
    }
}

// ---------------------------------------------------------------------------
// Kernel 3: adj-GEMM (s2), BK=16, adj generated on the fly, reg double-buffer.
// ---------------------------------------------------------------------------
__global__ void __launch_bounds__(256, 2)
sgemm_adj(const float* __restrict__ loc,
          const float* __restrict__ Hin,
          const float* __restrict__ bias,
          float* __restrict__ Out)
{
    __shared__ float As[2][16][128];
    __shared__ float Bs[2][16][128];
    __shared__ float lnx[128], lny[128];

    const int b = blockIdx.z;
    const float* locb = loc + (long)b * N_ * 2;
    const float* Bb   = Hin + (long)b * N_ * HID_;
    float*       Cb   = Out + (long)b * N_ * HID_;

    const int m0 = blockIdx.y * 128;
    const int n0 = blockIdx.x * 128;
    const int tid = threadIdx.x;
    const int ty = tid >> 4, tx = tid & 15;
    const int bRow = tid >> 4, bCol = (tid & 15) * 8;

    const int kbase = tid >> 7;          // 0 or 1
    const int mcol  = tid & 127;

    if (tid < 128) {
        lnx[tid] = locb[(m0 + tid) * 2 + 0];
        lny[tid] = locb[(m0 + tid) * 2 + 1];
    }
    __syncthreads();

    const int nk = N_ >> 4;

    unsigned long long acc2[4][8];
#pragma unroll
    for (int i = 0; i < 4; i++)
#pragma unroll
        for (int j = 0; j < 8; j++) acc2[i][j] = 0ull;

    // prologue: chunk 0
    {
        const float lx = lnx[mcol], ly = lny[mcol];
#pragma unroll
        for (int i = 0; i < 8; i++) {
            const int k = kbase + 2 * i;
            const float dxx = __fsub_rn(lx, locb[2 * k + 0]);
            const float dyy = __fsub_rn(ly, locb[2 * k + 1]);
            const float d2 = __fadd_rn(__fmul_rn(dxx, dxx), __fmul_rn(dyy, dyy));
            As[0][k][mcol] = rcpa(__fadd_rn(1.0f, __fmul_rn(0.5f, d2)));
        }
        const float* bp = Bb + (long)bRow * HID_ + n0 + bCol;
        *(float4*)&Bs[0][bRow][bCol]     = *(const float4*)(bp);
        *(float4*)&Bs[0][bRow][bCol + 4] = *(const float4*)(bp + 4);
    }
    __syncthreads();

    for (int t = 0; t < nk; t++) {
        const int buf = t & 1;
        const bool more = (t + 1 < nk);
        float4 b0v, b1v;
        float nextAdj[8];
        if (more) {
            const int k0 = (t + 1) << 4;
            const float* bp = Bb + (long)(k0 + bRow) * HID_ + n0 + bCol;
            b0v = *(const float4*)(bp);
            b1v = *(const float4*)(bp + 4);
            const float lx = lnx[mcol], ly = lny[mcol];
#pragma unroll
            for (int i = 0; i < 8; i++) {
                const int k = k0 + kbase + 2 * i;
                const float dxx = __fsub_rn(lx, locb[2 * k + 0]);
                const float dyy = __fsub_rn(ly, locb[2 * k + 1]);
                const float d2 = __fadd_rn(__fmul_rn(dxx, dxx), __fmul_rn(dyy, dyy));
                nextAdj[i] = rcpa(__fadd_rn(1.0f, __fmul_rn(0.5f, d2)));
            }
        }

#pragma unroll
        for (int k = 0; k < 16; k++) {
            unsigned long long a2[4];
#pragma unroll
            for (int i = 0; i < 4; i++)
                a2[i] = *(const unsigned long long*)&As[buf][k][ty * 8 + 2 * i];
            float4 c0 = *(const float4*)&Bs[buf][k][tx * 8];
            float4 c1 = *(const float4*)&Bs[buf][k][tx * 8 + 4];
            unsigned long long bd[8];
            bd[0] = pack2(c0.x, c0.x); bd[1] = pack2(c0.y, c0.y);
            bd[2] = pack2(c0.z, c0.z); bd[3] = pack2(c0.w, c0.w);
            bd[4] = pack2(c1.x, c1.x); bd[5] = pack2(c1.y, c1.y);
            bd[6] = pack2(c1.z, c1.z); bd[7] = pack2(c1.w, c1.w);
#pragma unroll
            for (int i = 0; i < 4; i++)
#pragma unroll
                for (int j = 0; j < 8; j++)
                    fma2(acc2[i][j], a2[i], bd[j]);
        }

        if (more) {
            const int nb = buf ^ 1;
#pragma unroll
            for (int i = 0; i < 8; i++)
                As[nb][kbase + 2 * i][mcol] = nextAdj[i];
            *(float4*)&Bs[nb][bRow][bCol]     = b0v;
            *(float4*)&Bs[nb][bRow][bCol + 4] = b1v;
        }
        __syncthreads();
    }

#pragma unroll
    for (int i = 0; i < 4; i++) {
        float lo[8], hi[8];
#pragma unroll
        for (int j = 0; j < 8; j++) {
            unpack2(acc2[i][j], lo[j], hi[j]);
            const float bb = bias[n0 + tx * 8 + j];
            lo[j] = fmaxf(__fadd_rn(lo[j], bb), 0.0f);
            hi[j] = fmaxf(__fadd_rn(hi[j], bb), 0.0f);
        }
        float* cp0 = Cb + (long)(m0 + ty * 8 + 2 * i) * HID_ + n0 + tx * 8;
        float* cp1 = cp0 + HID_;
        *(float4*)(cp0)     = make_float4(lo[0], lo[1], lo[2], lo[3]);
        *(float4*)(cp0 + 4) = make_float4(lo[4], lo[5], lo[6], lo[7]);
        *(float4*)(cp1)     = make_float4(hi[0], hi[1], hi[2], hi[3]);
        *(float4*)(cp1 + 4) = make_float4(hi[4], hi[5], hi[6], hi[7]);
    }
}

// ---------------------------------------------------------------------------
// Kernel 4: softmax over batch axis for e1, e2; sig[b,s] = sum_h(g1+g2)
// ---------------------------------------------------------------------------
__global__ void softmax_sig_kernel(const float* __restrict__ e1,
                                   const float* __restrict__ e2,
                                   float* __restrict__ sig)
{
    const int s = blockIdx.x;
    const int h = threadIdx.x;
    const long base = (long)s * HID_ + h;
    const long bs = (long)SIG_ * HID_;

    float m1 = -1e30f, m2 = -1e30f;
    for (int b = 0; b < B_; b++) {
        m1 = fmaxf(m1, e1[base + (long)b * bs]);
        m2 = fmaxf(m2, e2[base + (long)b * bs]);
    }
    float d1 = 0.0f, d2 = 0.0f;
    for (int b = 0; b < B_; b++) {
        d1 += __nv_expf(e1[base + (long)b * bs] - m1);
        d2 += __nv_expf(e2[base + (long)b * bs] - m2);
    }
    const float i1 = 1.0f / d1, i2 = 1.0f / d2;

    __shared__ float red[8];
    const int lane = h & 31, warp = h >> 5;
    for (int b = 0; b < B_; b++) {
        float c = __nv_expf(e1[base + (long)b * bs] - m1) * i1
                + __nv_expf(e2[base + (long)b * bs] - m2) * i2;
#pragma unroll
        for (int o = 16; o > 0; o >>= 1) c += __shfl_down_sync(0xffffffffu, c, o);
        if (lane == 0) red[warp] = c;
        __syncthreads();
        if (h == 0) {
            float t = 0.0f;
#pragma unroll
            for (int w = 0; w < 8; w++) t += red[w];
            sig[(long)b * SIG_ + s] = t;
        }
        __syncthreads();
    }
}

// ---------------------------------------------------------------------------
// Kernel 5: out[b,:] = softmax(sig[b,:] @ fcf_w^T + fcf_b). One warp per batch.
// ---------------------------------------------------------------------------
__global__ void final_kernel(const float* __restrict__ sig,
                             const float* __restrict__ fw,
                             const float* __restrict__ fb,
                             float* __restrict__ out)
{
    const int b = blockIdx.x;
    const int lane = threadIdx.x;
    float logits[OUT_];
#pragma unroll
    for (int o = 0; o < OUT_; o++) {
        float p = 0.0f;
        for (int s = lane; s < SIG_; s += 32)
            p = __fmaf_rn(sig[(long)b * SIG_ + s], fw[(long)o * SIG_ + s], p);
#pragma unroll
        for (int off = 16; off > 0; off >>= 1)
            p += __shfl_down_sync(0xffffffffu, p, off);
        p = __shfl_sync(0xffffffffu, p, 0);
        logits[o] = p + fb[o];
    }
    if (lane == 0) {
        float mx = -1e30f;
#pragma unroll
        for (int o = 0; o < OUT_; o++) mx = fmaxf(mx, logits[o]);
        float e[OUT_], ssum = 0.0f;
#pragma unroll
        for (int o = 0; o < OUT_; o++) { e[o] = __nv_expf(logits[o] - mx); ssum += e[o]; }
        const float inv = 1.0f / ssum;
#pragma unroll
        for (int o = 0; o < OUT_; o++) out[(long)b * OUT_ + o] = e[o] * inv;
    }
}

// ---------------------------------------------------------------------------
extern "C" void kernel_launch(void* const* d_in, const int* in_sizes, int n_in,
                              void* d_out, int out_size)
{
    const float* x     = (const float*)d_in[0];
    const float* z     = (const float*)d_in[2];
    const float* mg    = (const float*)d_in[3];
    const float* gc1w  = (const float*)d_in[4];
    const float* gc1b  = (const float*)d_in[5];
    const float* gc2w  = (const float*)d_in[6];
    const float* gc2b  = (const float*)d_in[7];
    const float* coll1 = (const float*)d_in[8];
    const float* coll2 = (const float*)d_in[9];
    const float* fcfw  = (const float*)d_in[10];
    const float* fcfb  = (const float*)d_in[11];
    float* outp = (float*)d_out;

    float *prmf, *loc, *feat, *bufA, *bufB, *bufC, *e1, *e2, *sig;
    double* logc;
    cudaGetSymbolAddress((void**)&prmf, g_prmf);
    cudaGetSymbolAddress((void**)&logc, g_logc);
    cudaGetSymbolAddress((void**)&loc,  g_loc);
    cudaGetSymbolAddress((void**)&feat, g_feat);
    cudaGetSymbolAddress((void**)&bufA, g_bufA);
    cudaGetSymbolAddress((void**)&bufB, g_bufB);
    cudaGetSymbolAddress((void**)&bufC, g_bufC);
    cudaGetSymbolAddress((void**)&e1,   g_e1);
    cudaGetSymbolAddress((void**)&e2,   g_e2);
    cudaGetSymbolAddress((void**)&sig,  g_sig);

    static cudaStream_t s1s = nullptr;
    static cudaEvent_t evA = nullptr, ev1 = nullptr;
    if (s1s == nullptr) {
        cudaStreamCreateWithFlags(&s1s, cudaStreamNonBlocking);
        cudaEventCreateWithFlags(&evA, cudaEventDisableTiming);
        cudaEventCreateWithFlags(&ev1, cudaEventDisableTiming);
    }

    const long BS = (long)N_ * HID_;
    const long ES = (long)SIG_ * HID_;

    prep_kernel<<<1, 32>>>(mg, prmf, logc);
    sampler_kernel<<<B_, N_>>>(x, z, prmf, logc, loc, feat, outp + B_ * OUT_);
    adj_feat_s1_kernel<<<B_, N_>>>(loc, feat, gc1w, gc1b, bufB);   // s1

    // fork: e1 = coll1 @ s1 on side stream (overlaps t1 -> s2 chain)
    cudaEventRecord(evA, 0);
    cudaStreamWaitEvent(s1s, evA, 0);
    sgemm128<<<dim3(2, 2, B_), 256, 0, s1s>>>(coll1, 512, 0, bufB, 256, BS, e1, 256, ES);
    cudaEventRecord(ev1, s1s);

    // main chain
    sgemm128<<<dim3(2, 4, B_), 256>>>(bufB, 256, BS, gc2w, 256, 0, bufA, 256, BS);  // t1
    sgemm_adj<<<dim3(2, 4, B_), 256>>>(loc, bufA, gc2b, bufC);                      // s2
    sgemm128<<<dim3(2, 2, B_), 256>>>(coll2, 512, 0, bufC, 256, BS, e2, 256, ES);   // e2

    // join
    cudaStreamWaitEvent(0, ev1, 0);
    softmax_sig_kernel<<<SIG_, HID_>>>(e1, e2, sig);
    final_kernel<<<B_, 32>>>(sig, fcfw, fcfb, outp);
}

// round 15
// speedup vs baseline: 1.2335x; 1.1389x over previous
#include <cuda_runtime.h>
#include <math.h>

#define B_    256
#define N_    512
#define SIG_  256
#define HID_  256
#define OUT_  10
#define H_    256

extern "C" __device__ float __nv_expf(float);

// ---------------- scratch (static device globals; no allocation) ----------------
__device__ float  g_prmf[16 * 8];
__device__ double g_logc[16];
__device__ float  g_loc [B_ * N_ * 2];
__device__ float  g_feat[B_ * N_ * 3];
__device__ float  g_bufA[B_ * N_ * HID_];      // t1
__device__ float  g_bufB[B_ * N_ * HID_];      // s1
__device__ float  g_bufC[B_ * N_ * HID_];      // s2
__device__ float  g_e1  [B_ * SIG_ * HID_];
__device__ float  g_e2  [B_ * SIG_ * HID_];
__device__ float  g_sig [B_ * SIG_];

// ---------------- packed f32x2 helpers (sm_103a) ----------------
__device__ __forceinline__ unsigned long long pack2(float lo, float hi)
{
    unsigned long long r;
    asm("mov.b64 %0, {%1, %2};" : "=l"(r) : "f"(lo), "f"(hi));
    return r;
}
__device__ __forceinline__ void unpack2(unsigned long long v, float& lo, float& hi)
{
    asm("mov.b64 {%0, %1}, %2;" : "=f"(lo), "=f"(hi) : "l"(v));
}
__device__ __forceinline__ void fma2(unsigned long long& acc,
                                     unsigned long long a, unsigned long long b)
{
    asm("fma.rn.f32x2 %0, %1, %2, %0;" : "+l"(acc) : "l"(a), "l"(b));
}
__device__ __forceinline__ float rcpa(float x)
{
    float r; asm("rcp.approx.f32 %0, %1;" : "=f"(r) : "f"(x)); return r;
}

// ---------------------------------------------------------------------------
// FROZEN decision-chain functions (validated R10). DO NOT TOUCH.
// ---------------------------------------------------------------------------
__device__ __forceinline__ float tanh_rational_fma(float x)
{
    const float kClamp = 7.90531110763549805f;
    float xc = fminf(fmaxf(x, -kClamp), kClamp);
    float x2 = __fmul_rn(xc, xc);
    float p = -2.76076847742355e-16f;
    p = __fmaf_rn(x2, p,  2.00018790482477e-13f);
    p = __fmaf_rn(x2, p, -8.60467152213735e-11f);
    p = __fmaf_rn(x2, p,  5.12229709037114e-08f);
    p = __fmaf_rn(x2, p,  1.48572235717979e-05f);
    p = __fmaf_rn(x2, p,  6.37261928875436e-04f);
    p = __fmaf_rn(x2, p,  4.89352455891786e-03f);
    float num = __fmul_rn(xc, p);
    float q = 1.19825839466702e-06f;
    q = __fmaf_rn(x2, q,  1.18534705686654e-04f);
    q = __fmaf_rn(x2, q,  2.26843463243900e-03f);
    q = __fmaf_rn(x2, q,  4.89352518554385e-03f);
    float r = __fdiv_rn(num, q);
    return (fabsf(x) < 0.0004f) ? x : r;
}

__device__ __forceinline__ float exp_cephes_fma(float x)
{
    const float kLog2e = 1.44269504088896341f;
    const float kC1 = 0.693359375f;
    const float kC2 = -2.12194440e-4f;
    float m = floorf(__fmaf_rn(x, kLog2e, 0.5f));
    float r = __fmaf_rn(m, -kC1, x);
    r = __fmaf_rn(m, -kC2, r);
    float r2 = __fmul_rn(r, r);
    float p = 1.9875691500E-4f;
    p = __fmaf_rn(p, r, 1.3981999507E-3f);
    p = __fmaf_rn(p, r, 8.3334519073E-3f);
    p = __fmaf_rn(p, r, 4.1665795894E-2f);
    p = __fmaf_rn(p, r, 1.6666665459E-1f);
    p = __fmaf_rn(p, r, 5.0000001201E-1f);
    p = __fmaf_rn(p, r2, r);
    p = __fadd_rn(p, 1.0f);
    int mi = (int)m;
    float two_m = __uint_as_float((unsigned)(mi + 127) << 23);
    return __fmul_rn(p, two_m);
}

// ---------------------------------------------------------------------------
// Kernel 0: per-group params (FROZEN decision bits)
// ---------------------------------------------------------------------------
__global__ void prep_kernel(const float* __restrict__ mg,
                            float* __restrict__ prm, double* __restrict__ logc)
{
    const int g = threadIdx.x;
    if (g >= 16) return;
    const float mux = mg[g * 6 + 1];
    const float muy = mg[g * 6 + 2];
    const float sx  = exp_cephes_fma(mg[g * 6 + 3]);
    const float sy  = exp_cephes_fma(mg[g * 6 + 4]);
    const float rho = tanh_rational_fma(mg[g * 6 + 5]);
    const float omr2 = __fsub_rn(1.0f, __fmul_rn(rho, rho));
    const float somr = __fsqrt_rn(omr2);
    prm[g * 8 + 0] = mux;  prm[g * 8 + 1] = muy;
    prm[g * 8 + 2] = sx;   prm[g * 8 + 3] = sy;
    prm[g * 8 + 4] = rho;  prm[g * 8 + 5] = somr;
    logc[g] = -1.8378770664093453 - log((double)sx * (double)sy)
              - 0.5 * log((double)omr2);
}

// ---------------------------------------------------------------------------
// Kernel 1: sampler (FROZEN decision chain)
// ---------------------------------------------------------------------------
__global__ void sampler_kernel(const float* __restrict__ x,
                               const float* __restrict__ z,
                               const float* __restrict__ prm,
                               const double* __restrict__ logcv,
                               float* __restrict__ loc,
                               float* __restrict__ feat,
                               float* __restrict__ flp)
{
    const int b = blockIdx.x;
    const int n = threadIdx.x;

    __shared__ float  s_feat[N_ * 3];
    __shared__ double s_red[N_];

    const int g = n >> 5;
    const float mux  = prm[g * 8 + 0];
    const float muy  = prm[g * 8 + 1];
    const float sx   = prm[g * 8 + 2];
    const float sy   = prm[g * 8 + 3];
    const float rho  = prm[g * 8 + 4];
    const float somr = prm[g * 8 + 5];

    const float z1 = z[((long)b * N_ + n) * 2 + 0];
    const float z2 = z[((long)b * N_ + n) * 2 + 1];

    const float xs = __fadd_rn(mux, __fmul_rn(sx, z1));
    const float tt = __fadd_rn(__fmul_rn(rho, z1), __fmul_rn(somr, z2));
    const float ys = __fadd_rn(muy, __fmul_rn(sy, tt));

    const float l0 = tanh_rational_fma(xs);
    const float l1 = tanh_rational_fma(ys);
    loc[((long)b * N_ + n) * 2 + 0] = l0;
    loc[((long)b * N_ + n) * 2 + 1] = l1;

    float p0f = __fsub_rn(__fmul_rn(__fmul_rn(0.5f, __fadd_rn(l0, 1.0f)), 256.0f), 0.1f);
    float p1f = __fsub_rn(__fmul_rn(__fmul_rn(0.5f, __fadd_rn(l1, 1.0f)), 256.0f), 0.1f);
    int p0 = (int)truncf(p0f);
    int p1 = (int)truncf(p1f);
    p0 = min(max(p0, 0), H_ - 1);
    p1 = min(max(p1, 0), H_ - 1);
    const float pv = x[(long)b * H_ * H_ + (long)p0 * H_ + p1];

    s_feat[n * 3 + 0] = pv;
    s_feat[n * 3 + 1] = l0;
    s_feat[n * 3 + 2] = l1;

    {
        const double dx = (double)xs - (double)mux;
        const double dy = (double)ys - (double)muy;
        const double sxd = (double)sx, syd = (double)sy, rhod = (double)rho;
        const double omr2 = 1.0 - rhod * rhod;
        const double quad = (dx * dx / (sxd * sxd)
                             - 2.0 * rhod * dx * dy / (sxd * syd)
                             + dy * dy / (syd * syd)) / omr2;
        s_red[n] = logcv[g] - 0.5 * quad;
    }
    __syncthreads();
    for (int st = 256; st > 0; st >>= 1) {
        if (n < st) s_red[n] += s_red[n + st];
        __syncthreads();
    }
    if (n == 0) flp[b] = (float)s_red[0];

    float* fb = feat + (long)b * (N_ * 3);
    for (int i = n; i < N_ * 3; i += N_) fb[i] = s_feat[i];
}

// ---------------------------------------------------------------------------
// Kernel 1b: g = adj @ feat (3 cols), s1 = relu(g @ W1 + b1)
// ---------------------------------------------------------------------------
__global__ void __launch_bounds__(512)
adj_feat_s1_kernel(const float* __restrict__ loc,
                   const float* __restrict__ feat,
                   const float* __restrict__ gc1w,
                   const float* __restrict__ gc1b,
                   float* __restrict__ s1)
{
    const int b = blockIdx.x;
    const int n = threadIdx.x;

    __shared__ float lx[N_], ly[N_];
    __shared__ float fm[N_ * 3];
    __shared__ float w[3 * HID_];
    __shared__ float bias[HID_];
    __shared__ float gsm[N_ * 3];

    const float* locb = loc + (long)b * N_ * 2;
    const float* fb   = feat + (long)b * N_ * 3;

    lx[n] = locb[2 * n + 0];
    ly[n] = locb[2 * n + 1];
    for (int i = n; i < N_ * 3; i += N_) fm[i] = fb[i];
    for (int i = n; i < 3 * HID_; i += N_) w[i] = gc1w[i];
    if (n < HID_) bias[n] = gc1b[n];
    __syncthreads();

    const float myx = lx[n], myy = ly[n];
    float g0 = 0.0f, g1 = 0.0f, g2 = 0.0f;
#pragma unroll 4
    for (int m = 0; m < N_; m++) {
        const float dxx = __fsub_rn(myx, lx[m]);
        const float dyy = __fsub_rn(myy, ly[m]);
        const float d2  = __fadd_rn(__fmul_rn(dxx, dxx), __fmul_rn(dyy, dyy));
        const float a   = rcpa(__fmaf_rn(0.5f, d2, 1.0f));
        g0 = __fmaf_rn(a, fm[m * 3 + 0], g0);
        g1 = __fmaf_rn(a, fm[m * 3 + 1], g1);
        g2 = __fmaf_rn(a, fm[m * 3 + 2], g2);
    }
    gsm[n * 3 + 0] = g0;
    gsm[n * 3 + 1] = g1;
    gsm[n * 3 + 2] = g2;
    __syncthreads();

    float* s1b = s1 + (long)b * (N_ * HID_);
    for (int r = 0; r < 256; r++) {
        const int idx = r * N_ + n;
        const int nn = idx >> 8;
        const int hh = idx & (HID_ - 1);
        float v = __fmaf_rn(gsm[nn * 3 + 2], w[2 * HID_ + hh],
                  __fmaf_rn(gsm[nn * 3 + 1], w[HID_ + hh],
                  __fmaf_rn(gsm[nn * 3 + 0], w[hh], bias[hh])));
        s1b[idx] = fmaxf(v, 0.0f);
    }
}

// ---------------------------------------------------------------------------
// Kernel 2: batched SGEMM, 128x128, BK=16, thread tile 16(m)x4(n):
// warp = 1 row-group x 32 cols -> A loads fully broadcast (ulonglong2 pairs),
// B = one LDS.128 per k. 8 wavefronts per warp-k for 32 FFMA2 -> FMA-bound.
// Accumulation order identical (sequential k, lanewise fma.rn).
// ---------------------------------------------------------------------------
__global__ void __launch_bounds__(256, 2)
sgemm128(const float* __restrict__ A, int lda, long strideA,
         const float* __restrict__ Bm, int ldb, long strideB,
         float* __restrict__ C, int ldc, long strideC)
{
    __shared__ float As[2][16][128];
    __shared__ float Bs[2][16][128];

    const int bz = blockIdx.z;
    A  += (long)bz * strideA;
    Bm += (long)bz * strideB;
    C  += (long)bz * strideC;

    const int m0 = blockIdx.y * 128;
    const int n0 = blockIdx.x * 128;
    const int tid = threadIdx.x;
    const int ty = tid >> 5;               // 0..7  (16-row group)
    const int tx = tid & 31;               // 0..31 (4-col group)

    const int aRow = tid >> 1;             // 0..127
    const int aCol = (tid & 1) * 8;        // 0 or 8
    const int bRow = tid >> 4;             // 0..15
    const int bCol = (tid & 15) * 8;       // 0..120

    const int K = lda;
    const int nk = K >> 4;

    unsigned long long acc2[8][4];
#pragma unroll
    for (int i = 0; i < 8; i++)
#pragma unroll
        for (int j = 0; j < 4; j++) acc2[i][j] = 0ull;

    // prologue: chunk 0 -> buf 0
    {
        const float* ap = A + (long)(m0 + aRow) * lda + aCol;
        float4 a0 = *(const float4*)(ap);
        float4 a1 = *(const float4*)(ap + 4);
        As[0][aCol + 0][aRow] = a0.x; As[0][aCol + 1][aRow] = a0.y;
        As[0][aCol + 2][aRow] = a0.z; As[0][aCol + 3][aRow] = a0.w;
        As[0][aCol + 4][aRow] = a1.x; As[0][aCol + 5][aRow] = a1.y;
        As[0][aCol + 6][aRow] = a1.z; As[0][aCol + 7][aRow] = a1.w;
        const float* bp = Bm + (long)bRow * ldb + n0 + bCol;
        *(float4*)&Bs[0][bRow][bCol]     = *(const float4*)(bp);
        *(float4*)&Bs[0][bRow][bCol + 4] = *(const float4*)(bp + 4);
    }
    __syncthreads();

    for (int t = 0; t < nk; t++) {
        const int buf = t & 1;
        const bool more = (t + 1 < nk);
        float4 a0, a1, b0v, b1v;
        if (more) {
            const int k0 = (t + 1) << 4;
            const float* ap = A + (long)(m0 + aRow) * lda + k0 + aCol;
            a0 = *(const float4*)(ap);
            a1 = *(const float4*)(ap + 4);
            const float* bp = Bm + (long)(k0 + bRow) * ldb + n0 + bCol;
            b0v = *(const float4*)(bp);
            b1v = *(const float4*)(bp + 4);
        }

#pragma unroll
        for (int k = 0; k < 16; k++) {
            // A: 16 rows for this warp's row-group, as 8 packed row-pairs
            unsigned long long a2[8];
            {
                const float* arow = &As[buf][k][ty * 16];
                ulonglong2 p0 = *(const ulonglong2*)(arow);
                ulonglong2 p1 = *(const ulonglong2*)(arow + 4);
                ulonglong2 p2 = *(const ulonglong2*)(arow + 8);
                ulonglong2 p3 = *(const ulonglong2*)(arow + 12);
                a2[0] = p0.x; a2[1] = p0.y; a2[2] = p1.x; a2[3] = p1.y;
                a2[4] = p2.x; a2[5] = p2.y; a2[6] = p3.x; a2[7] = p3.y;
            }
            // B: 4 cols for this thread
            float4 c0 = *(const float4*)&Bs[buf][k][tx * 4];
            unsigned long long bd[4];
            bd[0] = pack2(c0.x, c0.x); bd[1] = pack2(c0.y, c0.y);
            bd[2] = pack2(c0.z, c0.z); bd[3] = pack2(c0.w, c0.w);
#pragma unroll
            for (int i = 0; i < 8; i++)
#pragma unroll
                for (int j = 0; j < 4; j++)
                    fma2(acc2[i][j], a2[i], bd[j]);
        }

        if (more) {
            const int nb = buf ^ 1;
            As[nb][aCol + 0][aRow] = a0.x; As[nb][aCol + 1][aRow] = a0.y;
            As[nb][aCol + 2][aRow] = a0.z; As[nb][aCol + 3][aRow] = a0.w;
            As[nb][aCol + 4][aRow] = a1.x; As[nb][aCol + 5][aRow] = a1.y;
            As[nb][aCol + 6][aRow] = a1.z; As[nb][aCol + 7][aRow] = a1.w;
            *(float4*)&Bs[nb][bRow][bCol]     = b0v;
            *(float4*)&Bs[nb][bRow][bCol + 4] = b1v;
        }
        __syncthreads();
    }

    // epilogue: thread owns rows m0+ty*16+2i(+1), cols n0+tx*4..+3
#pragma unroll
    for (int i = 0; i < 8; i++) {
        float lo[4], hi[4];
#pragma unroll
        for (int j = 0; j < 4; j++) unpack2(acc2[i][j], lo[j], hi[j]);
        float* cp0 = C + (long)(m0 + ty * 16 + 2 * i) * ldc + n0 + tx * 4;
        float* cp1 = cp0 + ldc;
        *(float4*)(cp0) = make_float4(lo[0], lo[1], lo[2], lo[3]);
        *(float4*)(cp1) = make_float4(hi[0], hi[1], hi[2], hi[3]);
    }
}

// ---------------------------------------------------------------------------
// Kernel 3: adj-GEMM (s2), BK=16, 16x4 thread tile, adj generated on the fly.
// ---------------------------------------------------------------------------
__global__ void __launch_bounds__(256, 2)
sgemm_adj(const float* __restrict__ loc,
          const float* __restrict__ Hin,
          const float* __restrict__ bias,
          float* __restrict__ Out)
{
    __shared__ float As[2][16][128];
    __shared__ float Bs[2][16][128];
    __shared__ float lnx[128], lny[128];

    const int b = blockIdx.z;
    const float* locb = loc + (long)b * N_ * 2;
    const float* Bb   = Hin + (long)b * N_ * HID_;
    float*       Cb   = Out + (long)b * N_ * HID_;

    const int m0 = blockIdx.y * 128;
    const int n0 = blockIdx.x * 128;
    const int tid = threadIdx.x;
    const int ty = tid >> 5, tx = tid & 31;
    const int bRow = tid >> 4, bCol = (tid & 15) * 8;

    const int kbase = tid >> 7;          // 0 or 1
    const int mcol  = tid & 127;

    if (tid < 128) {
        lnx[tid] = locb[(m0 + tid) * 2 + 0];
        lny[tid] = locb[(m0 + tid) * 2 + 1];
    }
    __syncthreads();

    const int nk = N_ >> 4;

    unsigned long long acc2[8][4];
#pragma unroll
    for (int i = 0; i < 8; i++)
#pragma unroll
        for (int j = 0; j < 4; j++) acc2[i][j] = 0ull;

    // prologue: chunk 0
    {
        const float lx = lnx[mcol], ly = lny[mcol];
#pragma unroll
        for (int i = 0; i < 8; i++) {
            const int k = kbase + 2 * i;
            const float dxx = __fsub_rn(lx, locb[2 * k + 0]);
            const float dyy = __fsub_rn(ly, locb[2 * k + 1]);
            const float d2 = __fadd_rn(__fmul_rn(dxx, dxx), __fmul_rn(dyy, dyy));
            As[0][k][mcol] = rcpa(__fadd_rn(1.0f, __fmul_rn(0.5f, d2)));
        }
        const float* bp = Bb + (long)bRow * HID_ + n0 + bCol;
        *(float4*)&Bs[0][bRow][bCol]     = *(const float4*)(bp);
        *(float4*)&Bs[0][bRow][bCol + 4] = *(const float4*)(bp + 4);
    }
    __syncthreads();

    for (int t = 0; t < nk; t++) {
        const int buf = t & 1;
        const bool more = (t + 1 < nk);
        float4 b0v, b1v;
        float nextAdj[8];
        if (more) {
            const int k0 = (t + 1) << 4;
            const float* bp = Bb + (long)(k0 + bRow) * HID_ + n0 + bCol;
            b0v = *(const float4*)(bp);
            b1v = *(const float4*)(bp + 4);
            const float lx = lnx[mcol], ly = lny[mcol];
#pragma unroll
            for (int i = 0; i < 8; i++) {
                const int k = k0 + kbase + 2 * i;
                const float dxx = __fsub_rn(lx, locb[2 * k + 0]);
                const float dyy = __fsub_rn(ly, locb[2 * k + 1]);
                const float d2 = __fadd_rn(__fmul_rn(dxx, dxx), __fmul_rn(dyy, dyy));
                nextAdj[i] = rcpa(__fadd_rn(1.0f, __fmul_rn(0.5f, d2)));
            }
        }

#pragma unroll
        for (int k = 0; k < 16; k++) {
            unsigned long long a2[8];
            {
                const float* arow = &As[buf][k][ty * 16];
                ulonglong2 p0 = *(const ulonglong2*)(arow);
                ulonglong2 p1 = *(const ulonglong2*)(arow + 4);
                ulonglong2 p2 = *(const ulonglong2*)(arow + 8);
                ulonglong2 p3 = *(const ulonglong2*)(arow + 12);
                a2[0] = p0.x; a2[1] = p0.y; a2[2] = p1.x; a2[3] = p1.y;
                a2[4] = p2.x; a2[5] = p2.y; a2[6] = p3.x; a2[7] = p3.y;
            }
            float4 c0 = *(const float4*)&Bs[buf][k][tx * 4];
            unsigned long long bd[4];
            bd[0] = pack2(c0.x, c0.x); bd[1] = pack2(c0.y, c0.y);
            bd[2] = pack2(c0.z, c0.z); bd[3] = pack2(c0.w, c0.w);
#pragma unroll
            for (int i = 0; i < 8; i++)
#pragma unroll
                for (int j = 0; j < 4; j++)
                    fma2(acc2[i][j], a2[i], bd[j]);
        }

        if (more) {
            const int nb = buf ^ 1;
#pragma unroll
            for (int i = 0; i < 8; i++)
                As[nb][kbase + 2 * i][mcol] = nextAdj[i];
            *(float4*)&Bs[nb][bRow][bCol]     = b0v;
            *(float4*)&Bs[nb][bRow][bCol + 4] = b1v;
        }
        __syncthreads();
    }

#pragma unroll
    for (int i = 0; i < 8; i++) {
        float lo[4], hi[4];
#pragma unroll
        for (int j = 0; j < 4; j++) {
            unpack2(acc2[i][j], lo[j], hi[j]);
            const float bb = bias[n0 + tx * 4 + j];
            lo[j] = fmaxf(__fadd_rn(lo[j], bb), 0.0f);
            hi[j] = fmaxf(__fadd_rn(hi[j], bb), 0.0f);
        }
        float* cp0 = Cb + (long)(m0 + ty * 16 + 2 * i) * HID_ + n0 + tx * 4;
        float* cp1 = cp0 + HID_;
        *(float4*)(cp0) = make_float4(lo[0], lo[1], lo[2], lo[3]);
        *(float4*)(cp1) = make_float4(hi[0], hi[1], hi[2], hi[3]);
    }
}

// ---------------------------------------------------------------------------
// Kernel 4: softmax over batch axis for e1, e2; sig[b,s] = sum_h(g1+g2)
// ---------------------------------------------------------------------------
__global__ void softmax_sig_kernel(const float* __restrict__ e1,
                                   const float* __restrict__ e2,
                                   float* __restrict__ sig)
{
    const int s = blockIdx.x;
    const int h = threadIdx.x;
    const long base = (long)s * HID_ + h;
    const long bs = (long)SIG_ * HID_;

    float m1 = -1e30f, m2 = -1e30f;
    for (int b = 0; b < B_; b++) {
        m1 = fmaxf(m1, e1[base + (long)b * bs]);
        m2 = fmaxf(m2, e2[base + (long)b * bs]);
    }
    float d1 = 0.0f, d2 = 0.0f;
    for (int b = 0; b < B_; b++) {
        d1 += __nv_expf(e1[base + (long)b * bs] - m1);
        d2 += __nv_expf(e2[base + (long)b * bs] - m2);
    }
    const float i1 = 1.0f / d1, i2 = 1.0f / d2;

    __shared__ float red[8];
    const int lane = h & 31, warp = h >> 5;
    for (int b = 0; b < B_; b++) {
        float c = __nv_expf(e1[base + (long)b * bs] - m1) * i1
                + __nv_expf(e2[base + (long)b * bs] - m2) * i2;
#pragma unroll
        for (int o = 16; o > 0; o >>= 1) c += __shfl_down_sync(0xffffffffu, c, o);
        if (lane == 0) red[warp] = c;
        __syncthreads();
        if (h == 0) {
            float t = 0.0f;
#pragma unroll
            for (int w = 0; w < 8; w++) t += red[w];
            sig[(long)b * SIG_ + s] = t;
        }
        __syncthreads();
    }
}

// ---------------------------------------------------------------------------
// Kernel 5: out[b,:] = softmax(sig[b,:] @ fcf_w^T + fcf_b). One warp per batch.
// ---------------------------------------------------------------------------
__global__ void final_kernel(const float* __restrict__ sig,
                             const float* __restrict__ fw,
                             const float* __restrict__ fb,
                             float* __restrict__ out)
{
    const int b = blockIdx.x;
    const int lane = threadIdx.x;
    float logits[OUT_];
#pragma unroll
    for (int o = 0; o < OUT_; o++) {
        float p = 0.0f;
        for (int s = lane; s < SIG_; s += 32)
            p = __fmaf_rn(sig[(long)b * SIG_ + s], fw[(long)o * SIG_ + s], p);
#pragma unroll
        for (int off = 16; off > 0; off >>= 1)
            p += __shfl_down_sync(0xffffffffu, p, off);
        p = __shfl_sync(0xffffffffu, p, 0);
        logits[o] = p + fb[o];
    }
    if (lane == 0) {
        float mx = -1e30f;
#pragma unroll
        for (int o = 0; o < OUT_; o++) mx = fmaxf(mx, logits[o]);
        float e[OUT_], ssum = 0.0f;
#pragma unroll
        for (int o = 0; o < OUT_; o++) { e[o] = __nv_expf(logits[o] - mx); ssum += e[o]; }
        const float inv = 1.0f / ssum;
#pragma unroll
        for (int o = 0; o < OUT_; o++) out[(long)b * OUT_ + o] = e[o] * inv;
    }
}

// ---------------------------------------------------------------------------
extern "C" void kernel_launch(void* const* d_in, const int* in_sizes, int n_in,
                              void* d_out, int out_size)
{
    const float* x     = (const float*)d_in[0];
    const float* z     = (const float*)d_in[2];
    const float* mg    = (const float*)d_in[3];
    const float* gc1w  = (const float*)d_in[4];
    const float* gc1b  = (const float*)d_in[5];
    const float* gc2w  = (const float*)d_in[6];
    const float* gc2b  = (const float*)d_in[7];
    const float* coll1 = (const float*)d_in[8];
    const float* coll2 = (const float*)d_in[9];
    const float* fcfw  = (const float*)d_in[10];
    const float* fcfb  = (const float*)d_in[11];
    float* outp = (float*)d_out;

    float *prmf, *loc, *feat, *bufA, *bufB, *bufC, *e1, *e2, *sig;
    double* logc;
    cudaGetSymbolAddress((void**)&prmf, g_prmf);
    cudaGetSymbolAddress((void**)&logc, g_logc);
    cudaGetSymbolAddress((void**)&loc,  g_loc);
    cudaGetSymbolAddress((void**)&feat, g_feat);
    cudaGetSymbolAddress((void**)&bufA, g_bufA);
    cudaGetSymbolAddress((void**)&bufB, g_bufB);
    cudaGetSymbolAddress((void**)&bufC, g_bufC);
    cudaGetSymbolAddress((void**)&e1,   g_e1);
    cudaGetSymbolAddress((void**)&e2,   g_e2);
    cudaGetSymbolAddress((void**)&sig,  g_sig);

    static cudaStream_t s1s = nullptr;
    static cudaEvent_t evA = nullptr, ev1 = nullptr;
    if (s1s == nullptr) {
        cudaStreamCreateWithFlags(&s1s, cudaStreamNonBlocking);
        cudaEventCreateWithFlags(&evA, cudaEventDisableTiming);
        cudaEventCreateWithFlags(&ev1, cudaEventDisableTiming);
    }

    const long BS = (long)N_ * HID_;
    const long ES = (long)SIG_ * HID_;

    prep_kernel<<<1, 32>>>(mg, prmf, logc);
    sampler_kernel<<<B_, N_>>>(x, z, prmf, logc, loc, feat, outp + B_ * OUT_);
    adj_feat_s1_kernel<<<B_, N_>>>(loc, feat, gc1w, gc1b, bufB);   // s1

    // fork: e1 = coll1 @ s1 on side stream (overlaps t1 -> s2 chain)
    cudaEventRecord(evA, 0);
    cudaStreamWaitEvent(s1s, evA, 0);
    sgemm128<<<dim3(2, 2, B_), 256, 0, s1s>>>(coll1, 512, 0, bufB, 256, BS, e1, 256, ES);
    cudaEventRecord(ev1, s1s);

    // main chain
    sgemm128<<<dim3(2, 4, B_), 256>>>(bufB, 256, BS, gc2w, 256, 0, bufA, 256, BS);  // t1
    sgemm_adj<<<dim3(2, 4, B_), 256>>>(loc, bufA, gc2b, bufC);                      // s2
    sgemm128<<<dim3(2, 2, B_), 256>>>(coll2, 512, 0, bufC, 256, BS, e2, 256, ES);   // e2

    // join
    cudaStreamWaitEvent(0, ev1, 0);
    softmax_sig_kernel<<<SIG_, HID_>>>(e1, e2, sig);
    final_kernel<<<B_, 32>>>(sig, fcfw, fcfb, outp);
}

// round 16
// speedup vs baseline: 1.2371x; 1.0029x over previous
#include <cuda_runtime.h>
#include <math.h>

#define B_    256
#define N_    512
#define SIG_  256
#define HID_  256
#define OUT_  10
#define H_    256

extern "C" __device__ float __nv_expf(float);

// ---------------- scratch (static device globals; no allocation) ----------------
__device__ float  g_prmf[16 * 8];
__device__ double g_logc[16];
__device__ float  g_loc [B_ * N_ * 2];
__device__ float  g_bufA[B_ * N_ * HID_];      // t1
__device__ float  g_bufB[B_ * N_ * HID_];      // s1
__device__ float  g_bufC[B_ * N_ * HID_];      // s2
__device__ float  g_e1  [B_ * SIG_ * HID_];
__device__ float  g_e2  [B_ * SIG_ * HID_];
__device__ float  g_sig [B_ * SIG_];

// ---------------- packed f32x2 helpers (sm_103a) ----------------
__device__ __forceinline__ unsigned long long pack2(float lo, float hi)
{
    unsigned long long r;
    asm("mov.b64 %0, {%1, %2};" : "=l"(r) : "f"(lo), "f"(hi));
    return r;
}
__device__ __forceinline__ void unpack2(unsigned long long v, float& lo, float& hi)
{
    asm("mov.b64 {%0, %1}, %2;" : "=f"(lo), "=f"(hi) : "l"(v));
}
__device__ __forceinline__ void fma2(unsigned long long& acc,
                                     unsigned long long a, unsigned long long b)
{
    asm("fma.rn.f32x2 %0, %1, %2, %0;" : "+l"(acc) : "l"(a), "l"(b));
}
__device__ __forceinline__ float rcpa(float x)
{
    float r; asm("rcp.approx.f32 %0, %1;" : "=f"(r) : "f"(x)); return r;
}

// ---------------------------------------------------------------------------
// FROZEN decision-chain functions (validated R10). DO NOT TOUCH.
// ---------------------------------------------------------------------------
__device__ __forceinline__ float tanh_rational_fma(float x)
{
    const float kClamp = 7.90531110763549805f;
    float xc = fminf(fmaxf(x, -kClamp), kClamp);
    float x2 = __fmul_rn(xc, xc);
    float p = -2.76076847742355e-16f;
    p = __fmaf_rn(x2, p,  2.00018790482477e-13f);
    p = __fmaf_rn(x2, p, -8.60467152213735e-11f);
    p = __fmaf_rn(x2, p,  5.12229709037114e-08f);
    p = __fmaf_rn(x2, p,  1.48572235717979e-05f);
    p = __fmaf_rn(x2, p,  6.37261928875436e-04f);
    p = __fmaf_rn(x2, p,  4.89352455891786e-03f);
    float num = __fmul_rn(xc, p);
    float q = 1.19825839466702e-06f;
    q = __fmaf_rn(x2, q,  1.18534705686654e-04f);
    q = __fmaf_rn(x2, q,  2.26843463243900e-03f);
    q = __fmaf_rn(x2, q,  4.89352518554385e-03f);
    float r = __fdiv_rn(num, q);
    return (fabsf(x) < 0.0004f) ? x : r;
}

__device__ __forceinline__ float exp_cephes_fma(float x)
{
    const float kLog2e = 1.44269504088896341f;
    const float kC1 = 0.693359375f;
    const float kC2 = -2.12194440e-4f;
    float m = floorf(__fmaf_rn(x, kLog2e, 0.5f));
    float r = __fmaf_rn(m, -kC1, x);
    r = __fmaf_rn(m, -kC2, r);
    float r2 = __fmul_rn(r, r);
    float p = 1.9875691500E-4f;
    p = __fmaf_rn(p, r, 1.3981999507E-3f);
    p = __fmaf_rn(p, r, 8.3334519073E-3f);
    p = __fmaf_rn(p, r, 4.1665795894E-2f);
    p = __fmaf_rn(p, r, 1.6666665459E-1f);
    p = __fmaf_rn(p, r, 5.0000001201E-1f);
    p = __fmaf_rn(p, r2, r);
    p = __fadd_rn(p, 1.0f);
    int mi = (int)m;
    float two_m = __uint_as_float((unsigned)(mi + 127) << 23);
    return __fmul_rn(p, two_m);
}

// ---------------------------------------------------------------------------
// Kernel 0: per-group params (FROZEN decision bits)
// ---------------------------------------------------------------------------
__global__ void prep_kernel(const float* __restrict__ mg,
                            float* __restrict__ prm, double* __restrict__ logc)
{
    const int g = threadIdx.x;
    if (g >= 16) return;
    const float mux = mg[g * 6 + 1];
    const float muy = mg[g * 6 + 2];
    const float sx  = exp_cephes_fma(mg[g * 6 + 3]);
    const float sy  = exp_cephes_fma(mg[g * 6 + 4]);
    const float rho = tanh_rational_fma(mg[g * 6 + 5]);
    const float omr2 = __fsub_rn(1.0f, __fmul_rn(rho, rho));
    const float somr = __fsqrt_rn(omr2);
    prm[g * 8 + 0] = mux;  prm[g * 8 + 1] = muy;
    prm[g * 8 + 2] = sx;   prm[g * 8 + 3] = sy;
    prm[g * 8 + 4] = rho;  prm[g * 8 + 5] = somr;
    logc[g] = -1.8378770664093453 - log((double)sx * (double)sy)
              - 0.5 * log((double)omr2);
}

// ---------------------------------------------------------------------------
// Kernel 1 (FUSED): sampler (FROZEN decision chain) + g = adj@feat +
// s1 = relu(g @ W1 + b1). One block per batch, 512 threads.
// feat/loc stay in smem (loc also written to global for the s2 adj-GEMM).
// ---------------------------------------------------------------------------
__global__ void __launch_bounds__(512)
sampler_s1_kernel(const float* __restrict__ x,
                  const float* __restrict__ z,
                  const float* __restrict__ prm,
                  const double* __restrict__ logcv,
                  const float* __restrict__ gc1w,
                  const float* __restrict__ gc1b,
                  float* __restrict__ loc,
                  float* __restrict__ s1,
                  float* __restrict__ flp)
{
    const int b = blockIdx.x;
    const int n = threadIdx.x;   // 0..511

    __shared__ float  lx[N_], ly[N_];
    __shared__ float  s_feat[N_ * 3];
    __shared__ float  w[3 * HID_];
    __shared__ float  bias[HID_];
    __shared__ float  gsm[N_ * 3];
    __shared__ double s_red[N_];

    const int g = n >> 5;
    const float mux  = prm[g * 8 + 0];
    const float muy  = prm[g * 8 + 1];
    const float sx   = prm[g * 8 + 2];
    const float sy   = prm[g * 8 + 3];
    const float rho  = prm[g * 8 + 4];
    const float somr = prm[g * 8 + 5];

    const float z1 = z[((long)b * N_ + n) * 2 + 0];
    const float z2 = z[((long)b * N_ + n) * 2 + 1];

    // FROZEN decision chain
    const float xs = __fadd_rn(mux, __fmul_rn(sx, z1));
    const float tt = __fadd_rn(__fmul_rn(rho, z1), __fmul_rn(somr, z2));
    const float ys = __fadd_rn(muy, __fmul_rn(sy, tt));

    const float l0 = tanh_rational_fma(xs);
    const float l1 = tanh_rational_fma(ys);
    loc[((long)b * N_ + n) * 2 + 0] = l0;
    loc[((long)b * N_ + n) * 2 + 1] = l1;
    lx[n] = l0;
    ly[n] = l1;

    float p0f = __fsub_rn(__fmul_rn(__fmul_rn(0.5f, __fadd_rn(l0, 1.0f)), 256.0f), 0.1f);
    float p1f = __fsub_rn(__fmul_rn(__fmul_rn(0.5f, __fadd_rn(l1, 1.0f)), 256.0f), 0.1f);
    int p0 = (int)truncf(p0f);
    int p1 = (int)truncf(p1f);
    p0 = min(max(p0, 0), H_ - 1);
    p1 = min(max(p1, 0), H_ - 1);
    const float pv = x[(long)b * H_ * H_ + (long)p0 * H_ + p1];

    s_feat[n * 3 + 0] = pv;
    s_feat[n * 3 + 1] = l0;
    s_feat[n * 3 + 2] = l1;

    // logprob in f64 (smooth; output 1 only)
    {
        const double dx = (double)xs - (double)mux;
        const double dy = (double)ys - (double)muy;
        const double sxd = (double)sx, syd = (double)sy, rhod = (double)rho;
        const double omr2 = 1.0 - rhod * rhod;
        const double quad = (dx * dx / (sxd * sxd)
                             - 2.0 * rhod * dx * dy / (sxd * syd)
                             + dy * dy / (syd * syd)) / omr2;
        s_red[n] = logcv[g] - 0.5 * quad;
    }
    // load W1/b1 while reduction barriers run
    for (int i = n; i < 3 * HID_; i += N_) w[i] = gc1w[i];
    if (n < HID_) bias[n] = gc1b[n];
    __syncthreads();
    for (int st = 256; st > 0; st >>= 1) {
        if (n < st) s_red[n] += s_red[n + st];
        __syncthreads();
    }
    if (n == 0) flp[b] = (float)s_red[0];

    // g = adj @ feat (3 cols), adj generated on the fly
    const float myx = lx[n], myy = ly[n];
    float g0 = 0.0f, g1 = 0.0f, g2 = 0.0f;
#pragma unroll 4
    for (int m = 0; m < N_; m++) {
        const float dxx = __fsub_rn(myx, lx[m]);
        const float dyy = __fsub_rn(myy, ly[m]);
        const float d2  = __fadd_rn(__fmul_rn(dxx, dxx), __fmul_rn(dyy, dyy));
        const float a   = rcpa(__fmaf_rn(0.5f, d2, 1.0f));
        g0 = __fmaf_rn(a, s_feat[m * 3 + 0], g0);
        g1 = __fmaf_rn(a, s_feat[m * 3 + 1], g1);
        g2 = __fmaf_rn(a, s_feat[m * 3 + 2], g2);
    }
    gsm[n * 3 + 0] = g0;
    gsm[n * 3 + 1] = g1;
    gsm[n * 3 + 2] = g2;
    __syncthreads();

    // s1[n,h] = relu(g[n]·W[:,h] + b1[h]) — h-major coalesced writes
    float* s1b = s1 + (long)b * (N_ * HID_);
    for (int r = 0; r < 256; r++) {
        const int idx = r * N_ + n;
        const int nn = idx >> 8;
        const int hh = idx & (HID_ - 1);
        float v = __fmaf_rn(gsm[nn * 3 + 2], w[2 * HID_ + hh],
                  __fmaf_rn(gsm[nn * 3 + 1], w[HID_ + hh],
                  __fmaf_rn(gsm[nn * 3 + 0], w[hh], bias[hh])));
        s1b[idx] = fmaxf(v, 0.0f);
    }
}

// ---------------------------------------------------------------------------
// Kernel 2: batched SGEMM, 128x128, BK=16, thread tile 16(m)x4(n),
// packed fma.rn.f32x2, register double-buffer.  (validated R15)
// ---------------------------------------------------------------------------
__global__ void __launch_bounds__(256, 2)
sgemm128(const float* __restrict__ A, int lda, long strideA,
         const float* __restrict__ Bm, int ldb, long strideB,
         float* __restrict__ C, int ldc, long strideC)
{
    __shared__ float As[2][16][128];
    __shared__ float Bs[2][16][128];

    const int bz = blockIdx.z;
    A  += (long)bz * strideA;
    Bm += (long)bz * strideB;
    C  += (long)bz * strideC;

    const int m0 = blockIdx.y * 128;
    const int n0 = blockIdx.x * 128;
    const int tid = threadIdx.x;
    const int ty = tid >> 5;
    const int tx = tid & 31;

    const int aRow = tid >> 1;
    const int aCol = (tid & 1) * 8;
    const int bRow = tid >> 4;
    const int bCol = (tid & 15) * 8;

    const int K = lda;
    const int nk = K >> 4;

    unsigned long long acc2[8][4];
#pragma unroll
    for (int i = 0; i < 8; i++)
#pragma unroll
        for (int j = 0; j < 4; j++) acc2[i][j] = 0ull;

    {
        const float* ap = A + (long)(m0 + aRow) * lda + aCol;
        float4 a0 = *(const float4*)(ap);
        float4 a1 = *(const float4*)(ap + 4);
        As[0][aCol + 0][aRow] = a0.x; As[0][aCol + 1][aRow] = a0.y;
        As[0][aCol + 2][aRow] = a0.z; As[0][aCol + 3][aRow] = a0.w;
        As[0][aCol + 4][aRow] = a1.x; As[0][aCol + 5][aRow] = a1.y;
        As[0][aCol + 6][aRow] = a1.z; As[0][aCol + 7][aRow] = a1.w;
        const float* bp = Bm + (long)bRow * ldb + n0 + bCol;
        *(float4*)&Bs[0][bRow][bCol]     = *(const float4*)(bp);
        *(float4*)&Bs[0][bRow][bCol + 4] = *(const float4*)(bp + 4);
    }
    __syncthreads();

    for (int t = 0; t < nk; t++) {
        const int buf = t & 1;
        const bool more = (t + 1 < nk);
        float4 a0, a1, b0v, b1v;
        if (more) {
            const int k0 = (t + 1) << 4;
            const float* ap = A + (long)(m0 + aRow) * lda + k0 + aCol;
            a0 = *(const float4*)(ap);
            a1 = *(const float4*)(ap + 4);
            const float* bp = Bm + (long)(k0 + bRow) * ldb + n0 + bCol;
            b0v = *(const float4*)(bp);
            b1v = *(const float4*)(bp + 4);
        }

#pragma unroll
        for (int k = 0; k < 16; k++) {
            unsigned long long a2[8];
            {
                const float* arow = &As[buf][k][ty * 16];
                ulonglong2 p0 = *(const ulonglong2*)(arow);
                ulonglong2 p1 = *(const ulonglong2*)(arow + 4);
                ulonglong2 p2 = *(const ulonglong2*)(arow + 8);
                ulonglong2 p3 = *(const ulonglong2*)(arow + 12);
                a2[0] = p0.x; a2[1] = p0.y; a2[2] = p1.x; a2[3] = p1.y;
                a2[4] = p2.x; a2[5] = p2.y; a2[6] = p3.x; a2[7] = p3.y;
            }
            float4 c0 = *(const float4*)&Bs[buf][k][tx * 4];
            unsigned long long bd[4];
            bd[0] = pack2(c0.x, c0.x); bd[1] = pack2(c0.y, c0.y);
            bd[2] = pack2(c0.z, c0.z); bd[3] = pack2(c0.w, c0.w);
#pragma unroll
            for (int i = 0; i < 8; i++)
#pragma unroll
                for (int j = 0; j < 4; j++)
                    fma2(acc2[i][j], a2[i], bd[j]);
        }

        if (more) {
            const int nb = buf ^ 1;
            As[nb][aCol + 0][aRow] = a0.x; As[nb][aCol + 1][aRow] = a0.y;
            As[nb][aCol + 2][aRow] = a0.z; As[nb][aCol + 3][aRow] = a0.w;
            As[nb][aCol + 4][aRow] = a1.x; As[nb][aCol + 5][aRow] = a1.y;
            As[nb][aCol + 6][aRow] = a1.z; As[nb][aCol + 7][aRow] = a1.w;
            *(float4*)&Bs[nb][bRow][bCol]     = b0v;
            *(float4*)&Bs[nb][bRow][bCol + 4] = b1v;
        }
        __syncthreads();
    }

#pragma unroll
    for (int i = 0; i < 8; i++) {
        float lo[4], hi[4];
#pragma unroll
        for (int j = 0; j < 4; j++) unpack2(acc2[i][j], lo[j], hi[j]);
        float* cp0 = C + (long)(m0 + ty * 16 + 2 * i) * ldc + n0 + tx * 4;
        float* cp1 = cp0 + ldc;
        *(float4*)(cp0) = make_float4(lo[0], lo[1], lo[2], lo[3]);
        *(float4*)(cp1) = make_float4(hi[0], hi[1], hi[2], hi[3]);
    }
}

// ---------------------------------------------------------------------------
// Kernel 3: adj-GEMM (s2), BK=16, 16x4 thread tile, adj generated on the fly.
// ---------------------------------------------------------------------------
__global__ void __launch_bounds__(256, 2)
sgemm_adj(const float* __restrict__ loc,
          const float* __restrict__ Hin,
          const float* __restrict__ bias,
          float* __restrict__ Out)
{
    __shared__ float As[2][16][128];
    __shared__ float Bs[2][16][128];
    __shared__ float lnx[128], lny[128];

    const int b = blockIdx.z;
    const float* locb = loc + (long)b * N_ * 2;
    const float* Bb   = Hin + (long)b * N_ * HID_;
    float*       Cb   = Out + (long)b * N_ * HID_;

    const int m0 = blockIdx.y * 128;
    const int n0 = blockIdx.x * 128;
    const int tid = threadIdx.x;
    const int ty = tid >> 5, tx = tid & 31;
    const int bRow = tid >> 4, bCol = (tid & 15) * 8;

    const int kbase = tid >> 7;          // 0 or 1
    const int mcol  = tid & 127;

    if (tid < 128) {
        lnx[tid] = locb[(m0 + tid) * 2 + 0];
        lny[tid] = locb[(m0 + tid) * 2 + 1];
    }
    __syncthreads();

    const int nk = N_ >> 4;

    unsigned long long acc2[8][4];
#pragma unroll
    for (int i = 0; i < 8; i++)
#pragma unroll
        for (int j = 0; j < 4; j++) acc2[i][j] = 0ull;

    {
        const float lx = lnx[mcol], ly = lny[mcol];
#pragma unroll
        for (int i = 0; i < 8; i++) {
            const int k = kbase + 2 * i;
            const float dxx = __fsub_rn(lx, locb[2 * k + 0]);
            const float dyy = __fsub_rn(ly, locb[2 * k + 1]);
            const float d2 = __fadd_rn(__fmul_rn(dxx, dxx), __fmul_rn(dyy, dyy));
            As[0][k][mcol] = rcpa(__fadd_rn(1.0f, __fmul_rn(0.5f, d2)));
        }
        const float* bp = Bb + (long)bRow * HID_ + n0 + bCol;
        *(float4*)&Bs[0][bRow][bCol]     = *(const float4*)(bp);
        *(float4*)&Bs[0][bRow][bCol + 4] = *(const float4*)(bp + 4);
    }
    __syncthreads();

    for (int t = 0; t < nk; t++) {
        const int buf = t & 1;
        const bool more = (t + 1 < nk);
        float4 b0v, b1v;
        float nextAdj[8];
        if (more) {
            const int k0 = (t + 1) << 4;
            const float* bp = Bb + (long)(k0 + bRow) * HID_ + n0 + bCol;
            b0v = *(const float4*)(bp);
            b1v = *(const float4*)(bp + 4);
            const float lx = lnx[mcol], ly = lny[mcol];
#pragma unroll
            for (int i = 0; i < 8; i++) {
                const int k = k0 + kbase + 2 * i;
                const float dxx = __fsub_rn(lx, locb[2 * k + 0]);
                const float dyy = __fsub_rn(ly, locb[2 * k + 1]);
                const float d2 = __fadd_rn(__fmul_rn(dxx, dxx), __fmul_rn(dyy, dyy));
                nextAdj[i] = rcpa(__fadd_rn(1.0f, __fmul_rn(0.5f, d2)));
            }
        }

#pragma unroll
        for (int k = 0; k < 16; k++) {
            unsigned long long a2[8];
            {
                const float* arow = &As[buf][k][ty * 16];
                ulonglong2 p0 = *(const ulonglong2*)(arow);
                ulonglong2 p1 = *(const ulonglong2*)(arow + 4);
                ulonglong2 p2 = *(const ulonglong2*)(arow + 8);
                ulonglong2 p3 = *(const ulonglong2*)(arow + 12);
                a2[0] = p0.x; a2[1] = p0.y; a2[2] = p1.x; a2[3] = p1.y;
                a2[4] = p2.x; a2[5] = p2.y; a2[6] = p3.x; a2[7] = p3.y;
            }
            float4 c0 = *(const float4*)&Bs[buf][k][tx * 4];
            unsigned long long bd[4];
            bd[0] = pack2(c0.x, c0.x); bd[1] = pack2(c0.y, c0.y);
            bd[2] = pack2(c0.z, c0.z); bd[3] = pack2(c0.w, c0.w);
#pragma unroll
            for (int i = 0; i < 8; i++)
#pragma unroll
                for (int j = 0; j < 4; j++)
                    fma2(acc2[i][j], a2[i], bd[j]);
        }

        if (more) {
            const int nb = buf ^ 1;
#pragma unroll
            for (int i = 0; i < 8; i++)
                As[nb][kbase + 2 * i][mcol] = nextAdj[i];
            *(float4*)&Bs[nb][bRow][bCol]     = b0v;
            *(float4*)&Bs[nb][bRow][bCol + 4] = b1v;
        }
        __syncthreads();
    }

#pragma unroll
    for (int i = 0; i < 8; i++) {
        float lo[4], hi[4];
#pragma unroll
        for (int j = 0; j < 4; j++) {
            unpack2(acc2[i][j], lo[j], hi[j]);
            const float bb = bias[n0 + tx * 4 + j];
            lo[j] = fmaxf(__fadd_rn(lo[j], bb), 0.0f);
            hi[j] = fmaxf(__fadd_rn(hi[j], bb), 0.0f);
        }
        float* cp0 = Cb + (long)(m0 + ty * 16 + 2 * i) * HID_ + n0 + tx * 4;
        float* cp1 = cp0 + HID_;
        *(float4*)(cp0) = make_float4(lo[0], lo[1], lo[2], lo[3]);
        *(float4*)(cp1) = make_float4(hi[0], hi[1], hi[2], hi[3]);
    }
}

// ---------------------------------------------------------------------------
// Kernel 4: softmax over batch axis for e1, e2; sig[b,s] = sum_h(g1+g2)
// ---------------------------------------------------------------------------
__global__ void softmax_sig_kernel(const float* __restrict__ e1,
                                   const float* __restrict__ e2,
                                   float* __restrict__ sig)
{
    const int s = blockIdx.x;
    const int h = threadIdx.x;
    const long base = (long)s * HID_ + h;
    const long bs = (long)SIG_ * HID_;

    float m1 = -1e30f, m2 = -1e30f;
    for (int b = 0; b < B_; b++) {
        m1 = fmaxf(m1, e1[base + (long)b * bs]);
        m2 = fmaxf(m2, e2[base + (long)b * bs]);
    }
    float d1 = 0.0f, d2 = 0.0f;
    for (int b = 0; b < B_; b++) {
        d1 += __nv_expf(e1[base + (long)b * bs] - m1);
        d2 += __nv_expf(e2[base + (long)b * bs] - m2);
    }
    const float i1 = 1.0f / d1, i2 = 1.0f / d2;

    __shared__ float red[8];
    const int lane = h & 31, warp = h >> 5;
    for (int b = 0; b < B_; b++) {
        float c = __nv_expf(e1[base + (long)b * bs] - m1) * i1
                + __nv_expf(e2[base + (long)b * bs] - m2) * i2;
#pragma unroll
        for (int o = 16; o > 0; o >>= 1) c += __shfl_down_sync(0xffffffffu, c, o);
        if (lane == 0) red[warp] = c;
        __syncthreads();
        if (h == 0) {
            float t = 0.0f;
#pragma unroll
            for (int w = 0; w < 8; w++) t += red[w];
            sig[(long)b * SIG_ + s] = t;
        }
        __syncthreads();
    }
}

// ---------------------------------------------------------------------------
// Kernel 5: out[b,:] = softmax(sig[b,:] @ fcf_w^T + fcf_b). One warp per batch.
// ---------------------------------------------------------------------------
__global__ void final_kernel(const float* __restrict__ sig,
                             const float* __restrict__ fw,
                             const float* __restrict__ fb,
                             float* __restrict__ out)
{
    const int b = blockIdx.x;
    const int lane = threadIdx.x;
    float logits[OUT_];
#pragma unroll
    for (int o = 0; o < OUT_; o++) {
        float p = 0.0f;
        for (int s = lane; s < SIG_; s += 32)
            p = __fmaf_rn(sig[(long)b * SIG_ + s], fw[(long)o * SIG_ + s], p);
#pragma unroll
        for (int off = 16; off > 0; off >>= 1)
            p += __shfl_down_sync(0xffffffffu, p, off);
        p = __shfl_sync(0xffffffffu, p, 0);
        logits[o] = p + fb[o];
    }
    if (lane == 0) {
        float mx = -1e30f;
#pragma unroll
        for (int o = 0; o < OUT_; o++) mx = fmaxf(mx, logits[o]);
        float e[OUT_], ssum = 0.0f;
#pragma unroll
        for (int o = 0; o < OUT_; o++) { e[o] = __nv_expf(logits[o] - mx); ssum += e[o]; }
        const float inv = 1.0f / ssum;
#pragma unroll
        for (int o = 0; o < OUT_; o++) out[(long)b * OUT_ + o] = e[o] * inv;
    }
}

// ---------------------------------------------------------------------------
extern "C" void kernel_launch(void* const* d_in, const int* in_sizes, int n_in,
                              void* d_out, int out_size)
{
    const float* x     = (const float*)d_in[0];
    const float* z     = (const float*)d_in[2];
    const float* mg    = (const float*)d_in[3];
    const float* gc1w  = (const float*)d_in[4];
    const float* gc1b  = (const float*)d_in[5];
    const float* gc2w  = (const float*)d_in[6];
    const float* gc2b  = (const float*)d_in[7];
    const float* coll1 = (const float*)d_in[8];
    const float* coll2 = (const float*)d_in[9];
    const float* fcfw  = (const float*)d_in[10];
    const float* fcfb  = (const float*)d_in[11];
    float* outp = (float*)d_out;

    float *prmf, *loc, *bufA, *bufB, *bufC, *e1, *e2, *sig;
    double* logc;
    cudaGetSymbolAddress((void**)&prmf, g_prmf);
    cudaGetSymbolAddress((void**)&logc, g_logc);
    cudaGetSymbolAddress((void**)&loc,  g_loc);
    cudaGetSymbolAddress((void**)&bufA, g_bufA);
    cudaGetSymbolAddress((void**)&bufB, g_bufB);
    cudaGetSymbolAddress((void**)&bufC, g_bufC);
    cudaGetSymbolAddress((void**)&e1,   g_e1);
    cudaGetSymbolAddress((void**)&e2,   g_e2);
    cudaGetSymbolAddress((void**)&sig,  g_sig);

    static cudaStream_t s1s = nullptr;
    static cudaEvent_t evA = nullptr, ev1 = nullptr;
    if (s1s == nullptr) {
        cudaStreamCreateWithFlags(&s1s, cudaStreamNonBlocking);
        cudaEventCreateWithFlags(&evA, cudaEventDisableTiming);
        cudaEventCreateWithFlags(&ev1, cudaEventDisableTiming);
    }

    const long BS = (long)N_ * HID_;
    const long ES = (long)SIG_ * HID_;

    prep_kernel<<<1, 32>>>(mg, prmf, logc);
    // fused: sampler + (adj@feat) + s1
    sampler_s1_kernel<<<B_, N_>>>(x, z, prmf, logc, gc1w, gc1b, loc, bufB,
                                  outp + B_ * OUT_);

    // fork: e1 = coll1 @ s1 on side stream (overlaps t1 -> s2 chain)
    cudaEventRecord(evA, 0);
    cudaStreamWaitEvent(s1s, evA, 0);
    sgemm128<<<dim3(2, 2, B_), 256, 0, s1s>>>(coll1, 512, 0, bufB, 256, BS, e1, 256, ES);
    cudaEventRecord(ev1, s1s);

    // main chain
    sgemm128<<<dim3(2, 4, B_), 256>>>(bufB, 256, BS, gc2w, 256, 0, bufA, 256, BS);  // t1
    sgemm_adj<<<dim3(2, 4, B_), 256>>>(loc, bufA, gc2b, bufC);                      // s2
    sgemm128<<<dim3(2, 2, B_), 256>>>(coll2, 512, 0, bufC, 256, BS, e2, 256, ES);   // e2

    // join
    cudaStreamWaitEvent(0, ev1, 0);
    softmax_sig_kernel<<<SIG_, HID_>>>(e1, e2, sig);
    final_kernel<<<B_, 32>>>(sig, fcfw, fcfb, outp);
}